// round 5
// baseline (speedup 1.0000x reference)
#include <cuda_runtime.h>
#include <math.h>

#define B_   4
#define N_   1024
#define K_   512
#define H_   8
#define DH_  64
#define HID_ 2048
#define KG_  (3*K_)          // 1536
#define BN_  (B_*N_)         // 4096
#define BNK_ (B_*N_*K_)      // 2097152
#define BHN_ (B_*H_*N_)      // 32768
#define NN_  (N_*N_)         // 1048576
#define QKVW_ (3*K_)         // 1536

// ---------------- device scratch (static, no allocation) ----------------
__device__ float g_gcat[K_*KG_];
__device__ float g_wqkv[K_*QKVW_];
__device__ float g_w2qk[K_*2*K_];
__device__ float g_ln1[BNK_];
__device__ float g_Z[BN_*KG_];
__device__ float g_a1[BNK_];
__device__ float g_mug[BNK_];
__device__ float g_qkv[BN_*QKVW_];
__device__ float g_s2[BN_*2*K_];
__device__ float g_inv[BNK_];
__device__ float g_qinv[BNK_];
__device__ float g_e[BNK_];
__device__ float g_gam[BHN_];
__device__ float g_del[BHN_];
__device__ float g_beta[33554432];   // B*H*N*N
__device__ float g_bm[B_*NN_];
__device__ float g_attn[BNK_];
__device__ float g_o[BNK_];
__device__ float g_res[BNK_];
__device__ float g_ln2[BNK_];
__device__ float g_h[BNK_];
__device__ float g_hid[BN_*HID_];
__device__ float g_bh[BNK_];

// ---------------- helpers ----------------
__device__ __forceinline__ float warpSum(float v) {
#pragma unroll
    for (int o = 16; o; o >>= 1) v += __shfl_down_sync(0xffffffffu, v, o);
    return v;
}
__device__ __forceinline__ float warpMax(float v) {
#pragma unroll
    for (int o = 16; o; o >>= 1) v = fmaxf(v, __shfl_down_sync(0xffffffffu, v, o));
    return v;
}
__device__ __forceinline__ unsigned f2tf(float x) {
    unsigned u;
    asm("cvt.rna.tf32.f32 %0, %1;" : "=r"(u) : "f"(x));
    return u;
}
__device__ __forceinline__ void cpa16(void* s, const void* g) {
    unsigned sa = (unsigned)__cvta_generic_to_shared(s);
    asm volatile("cp.async.cg.shared.global [%0], [%1], 16;" :: "r"(sa), "l"(g));
}

// ---------------- tf32 tensor-core GEMM, 3-stage cp.async, fused epilogues --------------
// BM=128, BK=16, 256 threads = 8 warps (4 x 2), warp tile 32 x WN.
// epi: 0 none; 1 gelu(acc+bias); 2 VFE update; 3 VFE update + final residual.
template<int BN, int WN, int NF>
__global__ __launch_bounds__(256, 2)
void gemm_tf32(const float* __restrict__ A, const float* __restrict__ Bm,
               float* __restrict__ C,
               int M, int N, int Kd, int lda, int ldb, int ldc,
               long long sAo, long long sAi, long long sBo, long long sBi,
               long long sCo, long long sCi, int innerDiv, int causal,
               int epi,
               const float* __restrict__ bias,
               const float* __restrict__ e_hin,  const float* __restrict__ e_prior,
               const float* __restrict__ e_aux,  const float* __restrict__ e_lr,
               const float* __restrict__ e_res,  const float* __restrict__ e_ln2)
{
    constexpr int BM = 128;
    constexpr int BK = 16;
    constexpr int LDA = BK + 4;      // 20
    constexpr int LDB = BN + 8;      // 136/72
    extern __shared__ float dsm[];
    float* sA = dsm;                         // 3 * BM*LDA
    float* sB = dsm + 3 * BM * LDA;          // 3 * BK*LDB

    int z = blockIdx.z;
    int zo = z / innerDiv, zi = z - zo * innerDiv;
    A  += zo * sAo + zi * sAi;
    Bm += zo * sBo + zi * sBi;
    C  += zo * sCo + zi * sCi;

    int tid = threadIdx.x;
    int wid = tid >> 5, lane = tid & 31;
    int wm = wid & 3, wn = wid >> 2;
    int row0 = blockIdx.y * BM, col0 = blockIdx.x * BN;
    int lr = lane >> 2, lc = lane & 3;

    float acc[2][NF][4];
#pragma unroll
    for (int mi = 0; mi < 2; mi++)
#pragma unroll
        for (int ni = 0; ni < NF; ni++)
#pragma unroll
            for (int r = 0; r < 4; r++) acc[mi][ni][r] = 0.f;

    int kTiles = Kd / BK;
    if (causal) {
        int lim = (row0 + BM) / BK;
        if (lim < kTiles) kTiles = lim;
    }

    auto loadTile = [&](int t, int buf) {
        int k0 = t * BK;
        float* pA = sA + buf * BM * LDA;
        float* pB = sB + buf * BK * LDB;
#pragma unroll
        for (int c = tid; c < BM * 4; c += 256) {
            int m = c >> 2, k4 = (c & 3) * 4;
            cpa16(&pA[m * LDA + k4],
                  A + (long long)(row0 + m) * lda + k0 + k4);
        }
#pragma unroll
        for (int c = tid; c < 4 * BN; c += 256) {
            int kk = c / (BN / 4), n4 = (c % (BN / 4)) * 4;
            cpa16(&pB[kk * LDB + n4],
                  Bm + (long long)(k0 + kk) * ldb + col0 + n4);
        }
        asm volatile("cp.async.commit_group;");
    };

    loadTile(0, 0);
    loadTile(1, 1);
    for (int t = 0; t < kTiles; t++) {
        asm volatile("cp.async.wait_group 1;");
        __syncthreads();
        if (t + 2 < kTiles) loadTile(t + 2, (t + 2) % 3);
        else asm volatile("cp.async.commit_group;");
        int buf = t % 3;
        const float* pA = sA + buf * BM * LDA;
        const float* pB = sB + buf * BK * LDB;
#pragma unroll
        for (int ks = 0; ks < 2; ks++) {
            int kb = ks * 8 + lc;
            unsigned a[2][4];
#pragma unroll
            for (int mi = 0; mi < 2; mi++) {
                int r = wm * 32 + mi * 16 + lr;
                a[mi][0] = f2tf(pA[r * LDA + kb]);
                a[mi][1] = f2tf(pA[(r + 8) * LDA + kb]);
                a[mi][2] = f2tf(pA[r * LDA + kb + 4]);
                a[mi][3] = f2tf(pA[(r + 8) * LDA + kb + 4]);
            }
#pragma unroll
            for (int ni = 0; ni < NF; ni++) {
                int cc = wn * WN + ni * 8 + lr;
                unsigned b0 = f2tf(pB[kb * LDB + cc]);
                unsigned b1 = f2tf(pB[(kb + 4) * LDB + cc]);
#pragma unroll
                for (int mi = 0; mi < 2; mi++) {
                    asm volatile(
                        "mma.sync.aligned.m16n8k8.row.col.f32.tf32.tf32.f32 "
                        "{%0,%1,%2,%3}, {%4,%5,%6,%7}, {%8,%9}, {%0,%1,%2,%3};"
                        : "+f"(acc[mi][ni][0]), "+f"(acc[mi][ni][1]),
                          "+f"(acc[mi][ni][2]), "+f"(acc[mi][ni][3])
                        : "r"(a[mi][0]), "r"(a[mi][1]), "r"(a[mi][2]), "r"(a[mi][3]),
                          "r"(b0), "r"(b1));
                }
            }
        }
    }

    auto epival = [&](float a, int r, int c) -> float {
        if (epi == 0) return a;
        float x = a + bias[c];
        if (epi == 1) {
            float x3 = x * x * x;
            return 0.5f * x * (1.f + tanhf(0.7978845608028654f * (x + 0.044715f * x3)));
        }
        long long off = (long long)r * ldc + c;
        float hv = e_hin[off];
        float val = hv + e_lr[0] * (x - (1e-3f * (hv - e_prior[off]) + (hv - e_aux[off])));
        if (epi == 3) val = e_res[off] + val - e_ln2[off];
        return val;
    };

#pragma unroll
    for (int mi = 0; mi < 2; mi++) {
#pragma unroll
        for (int ni = 0; ni < NF; ni++) {
            int r = row0 + wm * 32 + mi * 16 + lr;
            int cc = col0 + wn * WN + ni * 8 + 2 * lc;
            float2 v0, v1;
            v0.x = epival(acc[mi][ni][0], r, cc);
            v0.y = epival(acc[mi][ni][1], r, cc + 1);
            v1.x = epival(acc[mi][ni][2], r + 8, cc);
            v1.y = epival(acc[mi][ni][3], r + 8, cc + 1);
            *(float2*)&C[(long long)r * ldc + cc] = v0;
            *(float2*)&C[(long long)(r + 8) * ldc + cc] = v1;
        }
    }
}

// ---------------- prep kernels ----------------
__global__ void prep_gcat_kernel(const float* __restrict__ gen)
{
    int t = blockIdx.x * 256 + threadIdx.x;
    if (t >= K_ * KG_) return;
    int l = t / KG_, c = t - l * KG_;
    int g = c >> 9, k = c & (K_ - 1);
    g_gcat[t] = gen[((g * K_) + k) * K_ + l];
}

__global__ void prep_wqkv_kernel(const float* __restrict__ Wq, const float* __restrict__ Wk,
                                 const float* __restrict__ Wv)
{
    int t = blockIdx.x * 256 + threadIdx.x;
    if (t >= K_ * QKVW_) return;
    int l = t / QKVW_, c = t - l * QKVW_;
    int sel = c >> 9, cc = c & (K_ - 1);
    const float* W = (sel == 0) ? Wq : (sel == 1) ? Wk : Wv;
    g_wqkv[t] = W[l * K_ + cc];
}

__global__ void prep_w2qk_kernel(const float* __restrict__ Wq, const float* __restrict__ Wk)
{
    int t = blockIdx.x * 256 + threadIdx.x;
    if (t >= K_ * 2 * K_) return;
    int l = t / (2 * K_), c = t - l * 2 * K_;
    int sel = c >> 9, cc = c & (K_ - 1);
    float w = (sel == 0 ? Wq : Wk)[l * K_ + cc];
    g_w2qk[t] = w * w;
}

// ---------------- layernorm ----------------
__global__ void ln_kernel(const float* __restrict__ x, const float* __restrict__ gw,
                          const float* __restrict__ bw, float* __restrict__ y)
{
    int bn = blockIdx.x;
    const float* xr = x + (long long)bn * K_;
    float* yr = y + (long long)bn * K_;
    int t = threadIdx.x;
    float v0 = xr[t], v1 = xr[t + 256];
    __shared__ float red[8];
    __shared__ float s_mean, s_rstd;
    int lane = t & 31, w = t >> 5;
    float s = warpSum(v0 + v1);
    if (lane == 0) red[w] = s;
    __syncthreads();
    if (t == 0) {
        float tot = 0.f;
        for (int i = 0; i < 8; i++) tot += red[i];
        s_mean = tot * (1.f / 512.f);
    }
    __syncthreads();
    float m = s_mean;
    float d0 = v0 - m, d1 = v1 - m;
    float s2 = warpSum(d0 * d0 + d1 * d1);
    if (lane == 0) red[w] = s2;
    __syncthreads();
    if (t == 0) {
        float tot = 0.f;
        for (int i = 0; i < 8; i++) tot += red[i];
        s_rstd = rsqrtf(tot * (1.f / 512.f) + 1e-5f);
    }
    __syncthreads();
    float r = s_rstd;
    yr[t]       = d0 * r * gw[t]       + bw[t];
    yr[t + 256] = d1 * r * gw[t + 256] + bw[t + 256];
}

// ---------------- transport combines ----------------
__global__ void combine1_kernel(const float* __restrict__ phi, float sign)
{
    int i = blockIdx.x * 256 + threadIdx.x;
    if (i >= BNK_) return;
    int bn = i >> 9, k = i & (K_ - 1);
    const float* pp = phi + bn * 3;
    const float* z = g_Z + (long long)bn * KG_;
    g_a1[i] = sign * (pp[0] * z[k] + pp[1] * z[K_ + k] + pp[2] * z[2 * K_ + k]);
}

__global__ void combine2_kernel(const float* __restrict__ phi, float sign,
                                const float* __restrict__ xbase,
                                const float* __restrict__ resid,
                                float* __restrict__ outp)
{
    int i = blockIdx.x * 256 + threadIdx.x;
    if (i >= BNK_) return;
    int bn = i >> 9, k = i & (K_ - 1);
    const float* pp = phi + bn * 3;
    const float* z = g_Z + (long long)bn * KG_;
    float c = sign * (pp[0] * z[k] + pp[1] * z[K_ + k] + pp[2] * z[2 * K_ + k]);
    float r = xbase[i] + g_a1[i] + 0.5f * c;
    if (resid) r += resid[i];
    outp[i] = r;
}

// ---------------- fused attention prep + per-head gamma/delta reductions ----------------
__global__ void prep_attn_gamdel_kernel()
{
    int bn = blockIdx.x;                 // b*N + n
    int b = bn >> 10, n = bn & (N_ - 1);
    int t = threadIdx.x;
    int lane = t & 31;
    __shared__ float sacc[3][H_];
    if (t < 3 * H_) ((float*)sacc)[t] = 0.f;
    __syncthreads();

#pragma unroll
    for (int half = 0; half < 2; half++) {
        int k = t + half * 256;
        long long s2b = (long long)bn * (2 * K_);
        long long qb  = (long long)bn * QKVW_;
        long long ib  = (long long)bn * K_ + k;
        float sqraw = g_s2[s2b + k] + 1e-8f;
        float inv = 1.f / sqraw;
        float q = g_qkv[qb + k];
        g_inv[ib]  = inv;
        g_qinv[ib] = q * inv;
        float sk = g_s2[s2b + K_ + k] + 1e-8f;
        float kv = g_qkv[qb + K_ + k];
        g_e[ib] = sk + kv * kv;

        float qq  = q * q * inv;
        float lsq = logf(sqraw);
        float lsk = logf(sk);
        qq = warpSum(qq); lsq = warpSum(lsq); lsk = warpSum(lsk);
        if (lane == 0) {
            int h = k >> 6;
            atomicAdd(&sacc[0][h], qq);
            atomicAdd(&sacc[1][h], lsq);
            atomicAdd(&sacc[2][h], lsk);
        }
    }
    __syncthreads();
    if (t < H_) {
        int idx = ((b * H_ + t) * N_) + n;
        g_gam[idx] = -0.5f * (sacc[0][t] - (float)DH_ + sacc[1][t]);
        g_del[idx] = 0.5f * sacc[2][t];
    }
}

// ---------------- KL score kernel: tf32 mma, 64x64 tiles ----------------
__global__ __launch_bounds__(256) void score_kernel()
{
    int bh = blockIdx.z;
    int b = bh >> 3, h = bh & 7;
    int i0 = blockIdx.y * 64, j0 = blockIdx.x * 64;
    if (j0 > i0) return;               // fully masked tile: never read downstream

    constexpr int LDK = 68;
    __shared__ float Qs[64 * LDK];
    __shared__ float Ks[64 * LDK];
    int tid = threadIdx.x;
    int wid = tid >> 5, lane = tid & 31;
    int wm = wid & 3, wn = wid >> 2;
    int lr = lane >> 2, lc = lane & 3;
    int hoff = h * DH_;

    float acc[4][4] = {};

#pragma unroll
    for (int dc = 0; dc < 2; dc++) {
        for (int e = tid; e < 64 * 16; e += 256) {
            int r = e >> 4, c4 = (e & 15) * 4;
            long long qrow = (long long)(b * N_ + i0 + r);
            long long krow = (long long)(b * N_ + j0 + r);
            float4 qv, kv;
            if (dc == 0) {
                qv = *(const float4*)&g_inv[qrow * K_ + hoff + c4];
                qv.x *= -0.5f; qv.y *= -0.5f; qv.z *= -0.5f; qv.w *= -0.5f;
                kv = *(const float4*)&g_e[krow * K_ + hoff + c4];
            } else {
                qv = *(const float4*)&g_qinv[qrow * K_ + hoff + c4];
                kv = *(const float4*)&g_qkv[krow * QKVW_ + K_ + hoff + c4];
            }
            *(float4*)&Qs[r * LDK + c4] = qv;
            *(float4*)&Ks[r * LDK + c4] = kv;
        }
        __syncthreads();
#pragma unroll
        for (int ks = 0; ks < 8; ks++) {
            int kb = ks * 8 + lc;
            int ar = wm * 16 + lr;
            unsigned a0 = f2tf(Qs[ar * LDK + kb]);
            unsigned a1 = f2tf(Qs[(ar + 8) * LDK + kb]);
            unsigned a2 = f2tf(Qs[ar * LDK + kb + 4]);
            unsigned a3 = f2tf(Qs[(ar + 8) * LDK + kb + 4]);
#pragma unroll
            for (int ni = 0; ni < 4; ni++) {
                int bc = wn * 32 + ni * 8 + lr;
                unsigned b0 = f2tf(Ks[bc * LDK + kb]);
                unsigned b1 = f2tf(Ks[bc * LDK + kb + 4]);
                asm volatile(
                    "mma.sync.aligned.m16n8k8.row.col.f32.tf32.tf32.f32 "
                    "{%0,%1,%2,%3}, {%4,%5,%6,%7}, {%8,%9}, {%0,%1,%2,%3};"
                    : "+f"(acc[ni][0]), "+f"(acc[ni][1]),
                      "+f"(acc[ni][2]), "+f"(acc[ni][3])
                    : "r"(a0), "r"(a1), "r"(a2), "r"(a3), "r"(b0), "r"(b1));
            }
        }
        __syncthreads();
    }

    long long gdb = (long long)bh * N_;
#pragma unroll
    for (int half = 0; half < 2; half++) {
        int i = i0 + wm * 16 + lr + half * 8;
        float gv = g_gam[gdb + i];
#pragma unroll
        for (int ni = 0; ni < 4; ni++) {
            int j = j0 + wn * 32 + ni * 8 + 2 * lc;
            float2 o;
            o.x = acc[ni][half * 2 + 0] + gv + g_del[gdb + j];
            o.y = acc[ni][half * 2 + 1] + gv + g_del[gdb + j + 1];
            *(float2*)&g_beta[(gdb + i) * N_ + j] = o;
        }
    }
}

// ---------------- fused softmax (8 heads) + beta_m head-mean, causal-truncated ----------------
__global__ __launch_bounds__(256) void softmax_bm_kernel()
{
    int bi = blockIdx.x;               // b*N + i
    int b = bi >> 10, i = bi & (N_ - 1);
    int Jmax = ((i >> 7) + 1) << 7;
    int t = threadIdx.x;
    int lane = t & 31, w = t >> 5;
    __shared__ float red[8];
    __shared__ float s_val;
    float bmacc[4] = {0.f, 0.f, 0.f, 0.f};

    for (int h = 0; h < H_; h++) {
        float* p = g_beta + (((long long)(b * H_ + h)) * N_ + i) * N_;
        float ev[4];
        float m = -1e30f;
#pragma unroll
        for (int jj = 0; jj < 4; jj++) {
            int j = t + jj * 256;
            ev[jj] = (j <= i) ? p[j] : -1e30f;
            m = fmaxf(m, ev[jj]);
        }
        m = warpMax(m);
        if (lane == 0) red[w] = m;
        __syncthreads();
        if (t == 0) {
            float mm = red[0];
            for (int x = 1; x < 8; x++) mm = fmaxf(mm, red[x]);
            s_val = mm;
        }
        __syncthreads();
        m = s_val;
        float s = 0.f;
#pragma unroll
        for (int jj = 0; jj < 4; jj++) {
            ev[jj] = (t + jj * 256 <= i) ? expf(ev[jj] - m) : 0.f;
            s += ev[jj];
        }
        s = warpSum(s);
        if (lane == 0) red[w] = s;
        __syncthreads();
        if (t == 0) {
            float tot = 0.f;
            for (int x = 0; x < 8; x++) tot += red[x];
            s_val = 1.f / tot;
        }
        __syncthreads();
        float inv = s_val;
#pragma unroll
        for (int jj = 0; jj < 4; jj++) {
            int j = t + jj * 256;
            float v = ev[jj] * inv;
            if (j < Jmax) p[j] = v;
            bmacc[jj] += v;
        }
        __syncthreads();
    }

    float* bm = g_bm + ((long long)b * N_ + i) * N_;
#pragma unroll
    for (int jj = 0; jj < 4; jj++) {
        int j = t + jj * 256;
        if (j < Jmax) bm[j] = bmacc[jj] * 0.125f;
    }
}

// ---------------- host ----------------
static inline void launch_gemm(const float* A, const float* B, float* C,
                               int M, int N, int Kd, int lda, int ldb, int ldc,
                               long long sAo, long long sAi, long long sBo, long long sBi,
                               long long sCo, long long sCi, int innerDiv, int batch,
                               int causal = 0, int epi = 0,
                               const float* bias = nullptr,
                               const float* e_hin = nullptr, const float* e_prior = nullptr,
                               const float* e_aux = nullptr, const float* e_lr = nullptr,
                               const float* e_res = nullptr, const float* e_ln2 = nullptr)
{
    if (N % 128 == 0) {
        constexpr int SM = 3 * (128 * 20 + 16 * 136) * 4;   // 56832
        dim3 g(N / 128, M / 128, batch);
        gemm_tf32<128, 64, 8><<<g, 256, SM>>>(A, B, C, M, N, Kd, lda, ldb, ldc,
                                              sAo, sAi, sBo, sBi, sCo, sCi, innerDiv, causal,
                                              epi, bias, e_hin, e_prior, e_aux, e_lr, e_res, e_ln2);
    } else {
        constexpr int SM = 3 * (128 * 20 + 16 * 72) * 4;    // 44544
        dim3 g(N / 64, M / 128, batch);
        gemm_tf32<64, 32, 4><<<g, 256, SM>>>(A, B, C, M, N, Kd, lda, ldb, ldc,
                                             sAo, sAi, sBo, sBi, sCo, sCi, innerDiv, causal,
                                             epi, bias, e_hin, e_prior, e_aux, e_lr, e_res, e_ln2);
    }
}

extern "C" void kernel_launch(void* const* d_in, const int* in_sizes, int n_in,
                              void* d_out, int out_size)
{
    const float* mu_q     = (const float*)d_in[0];
    const float* sigma_q  = (const float*)d_in[1];
    const float* phi      = (const float*)d_in[2];
    const float* gen      = (const float*)d_in[3];
    const float* mu_prior = (const float*)d_in[5];
    const float* Wq  = (const float*)d_in[6];
    const float* Wk  = (const float*)d_in[7];
    const float* Wv  = (const float*)d_in[8];
    const float* Wo  = (const float*)d_in[9];
    const float* g1  = (const float*)d_in[10];
    const float* be1 = (const float*)d_in[11];
    const float* g2  = (const float*)d_in[12];
    const float* be2 = (const float*)d_in[13];
    const float* W1  = (const float*)d_in[14];
    const float* bh1 = (const float*)d_in[15];
    const float* W2  = (const float*)d_in[16];
    const float* bh2 = (const float*)d_in[17];
    const float* lr  = (const float*)d_in[18];

    static int attrDone = 0;
    if (!attrDone) {
        cudaFuncSetAttribute(gemm_tf32<128, 64, 8>,
                             cudaFuncAttributeMaxDynamicSharedMemorySize, 57344);
        cudaFuncSetAttribute(gemm_tf32<64, 32, 4>,
                             cudaFuncAttributeMaxDynamicSharedMemorySize, 45056);
        attrDone = 1;
    }

    void* tp;
#define GETSYM(var, sym) cudaGetSymbolAddress(&tp, sym); float* var = (float*)tp
    GETSYM(p_gcat, g_gcat);  GETSYM(p_wqkv, g_wqkv); GETSYM(p_w2qk, g_w2qk);
    GETSYM(p_ln1, g_ln1);    GETSYM(p_Z, g_Z);       GETSYM(p_a1, g_a1);
    GETSYM(p_mug, g_mug);    GETSYM(p_qkv, g_qkv);   GETSYM(p_s2, g_s2);
    GETSYM(p_beta, g_beta);  GETSYM(p_bm, g_bm);     GETSYM(p_attn, g_attn);
    GETSYM(p_o, g_o);        GETSYM(p_res, g_res);   GETSYM(p_ln2, g_ln2);
    GETSYM(p_h, g_h);        GETSYM(p_hid, g_hid);   GETSYM(p_bh, g_bh);
#undef GETSYM

    const int EW = 256;
    const int GB_BNK = BNK_ / EW;

    prep_gcat_kernel<<<(K_ * KG_ + EW - 1) / EW, EW>>>(gen);
    prep_wqkv_kernel<<<(K_ * QKVW_ + EW - 1) / EW, EW>>>(Wq, Wk, Wv);
    prep_w2qk_kernel<<<(K_ * 2 * K_ + EW - 1) / EW, EW>>>(Wq, Wk);

    // ---- attention sublayer ----
    ln_kernel<<<BN_, 256>>>(mu_q, g1, be1, p_ln1);

    launch_gemm(p_ln1, p_gcat, p_Z, BN_, KG_, K_, K_, KG_, KG_, 0,0,0,0,0,0, 1, 1);
    combine1_kernel<<<GB_BNK, EW>>>(phi, 1.f);
    launch_gemm(p_a1, p_gcat, p_Z, BN_, KG_, K_, K_, KG_, KG_, 0,0,0,0,0,0, 1, 1);
    combine2_kernel<<<GB_BNK, EW>>>(phi, 1.f, p_ln1, nullptr, p_mug);

    launch_gemm(p_mug, p_wqkv, p_qkv, BN_, QKVW_, K_, K_, QKVW_, QKVW_, 0,0,0,0,0,0, 1, 1);
    launch_gemm(sigma_q, p_w2qk, p_s2, BN_, 2 * K_, K_, K_, 2 * K_, 2 * K_, 0,0,0,0,0,0, 1, 1);

    prep_attn_gamdel_kernel<<<BN_, 256>>>();

    score_kernel<<<dim3(N_ / 64, N_ / 64, B_ * H_), 256>>>();
    softmax_bm_kernel<<<BN_, 256>>>();

    // out = beta @ v  (batched over b,h), causal K-truncation
    launch_gemm(p_beta, p_qkv + 2 * K_, p_attn, N_, DH_, N_, N_, QKVW_, K_,
                8LL * NN_, (long long)NN_,
                (long long)N_ * QKVW_, 64,
                (long long)N_ * K_, 64, H_, B_ * H_, 1);

    launch_gemm(p_attn, Wo, p_o, BN_, K_, K_, K_, K_, K_, 0,0,0,0,0,0, 1, 1);
    launch_gemm(p_o, p_gcat, p_Z, BN_, KG_, K_, K_, KG_, KG_, 0,0,0,0,0,0, 1, 1);
    combine1_kernel<<<GB_BNK, EW>>>(phi, -1.f);
    launch_gemm(p_a1, p_gcat, p_Z, BN_, KG_, K_, K_, KG_, KG_, 0,0,0,0,0,0, 1, 1);
    combine2_kernel<<<GB_BNK, EW>>>(phi, -1.f, p_o, mu_q, p_res);

    // ---- FFN sublayer ----
    ln_kernel<<<BN_, 256>>>(p_res, g2, be2, p_ln2);
    float* out = (float*)d_out;

    // iteration 1: h -> g_h
    launch_gemm(p_bm, p_ln2, p_bh, N_, K_, N_, N_, K_, K_,
                (long long)NN_, 0, (long long)N_ * K_, 0, (long long)N_ * K_, 0,
                1, B_, 1);
    launch_gemm(p_ln2, W1, p_hid, BN_, HID_, K_, K_, HID_, HID_, 0,0,0,0,0,0, 1, 1,
                0, 1, bh1);
    launch_gemm(p_hid, W2, p_h, BN_, K_, HID_, HID_, K_, K_, 0,0,0,0,0,0, 1, 1,
                0, 2, bh2, p_ln2, mu_prior, p_bh, lr);

    // iteration 2: final residual fused, writes directly to out
    launch_gemm(p_bm, p_h, p_bh, N_, K_, N_, N_, K_, K_,
                (long long)NN_, 0, (long long)N_ * K_, 0, (long long)N_ * K_, 0,
                1, B_, 1);
    launch_gemm(p_h, W1, p_hid, BN_, HID_, K_, K_, HID_, HID_, 0,0,0,0,0,0, 1, 1,
                0, 1, bh1);
    launch_gemm(p_hid, W2, out, BN_, K_, HID_, HID_, K_, K_, 0,0,0,0,0,0, 1, 1,
                0, 3, bh2, p_h, mu_prior, p_bh, lr, p_res, p_ln2);

    // ---- remaining outputs: (sigma_q, phi) ----
    cudaMemcpyAsync(out + BNK_, sigma_q, (size_t)BNK_ * sizeof(float),
                    cudaMemcpyDeviceToDevice);
    cudaMemcpyAsync(out + 2 * (size_t)BNK_, phi, (size_t)B_ * N_ * 3 * sizeof(float),
                    cudaMemcpyDeviceToDevice);
}

// round 7
// speedup vs baseline: 1.6131x; 1.6131x over previous
#include <cuda_runtime.h>
#include <cuda_fp16.h>
#include <math.h>
#include <stdint.h>

#define B_   4
#define N_   1024
#define K_   512
#define H_   8
#define DH_  64
#define HID_ 2048
#define KG_  (3*K_)
#define BN_  (B_*N_)
#define BNK_ (B_*N_*K_)
#define BHN_ (B_*H_*N_)
#define NN_  (N_*N_)
#define QKVW_ (3*K_)

// ---------------- device scratch ----------------
__device__ __half h_gcatT[KG_*K_];
__device__ __half h_wqkvT[QKVW_*K_];
__device__ __half h_w2qkT[2*K_*K_];
__device__ __half h_WoT[K_*K_];
__device__ __half h_W1T[HID_*K_];
__device__ __half h_W2T[K_*HID_];
__device__ __half h_sig[BNK_];
__device__ __half h_ln1[BNK_];
__device__ __half h_a1[BNK_];
__device__ __half h_mug[BNK_];
__device__ __half h_attn[BNK_];
__device__ __half h_o[BNK_];
__device__ __half h_ln2[BNK_];
__device__ __half h_hh[BNK_];
__device__ __half h_hid[BN_*HID_];
__device__ __half h_beta[33554432];
__device__ __half h_bm[B_*NN_];
__device__ __half h_vT[BNK_];
__device__ __half h_ln2T[BNK_];
__device__ __half h_hT[BNK_];
__device__ float g_ln1[BNK_];
__device__ float g_Z[BN_*KG_];
__device__ float g_a1[BNK_];
__device__ float g_qkv[BN_*QKVW_];
__device__ float g_s2[BN_*2*K_];
__device__ float g_inv[BNK_];
__device__ float g_qinv[BNK_];
__device__ float g_e[BNK_];
__device__ float g_gam[BHN_];
__device__ float g_del[BHN_];
__device__ float g_beta[33554432];
__device__ float g_o[BNK_];
__device__ float g_res[BNK_];
__device__ float g_ln2[BNK_];
__device__ float g_h[BNK_];
__device__ float g_bh[BNK_];

// ---------------- helpers ----------------
__device__ __forceinline__ float warpSum(float v) {
#pragma unroll
    for (int o = 16; o; o >>= 1) v += __shfl_down_sync(0xffffffffu, v, o);
    return v;
}
__device__ __forceinline__ float warpMax(float v) {
#pragma unroll
    for (int o = 16; o; o >>= 1) v = fmaxf(v, __shfl_down_sync(0xffffffffu, v, o));
    return v;
}
__device__ __forceinline__ unsigned f2tf(float x) {
    unsigned u;
    asm("cvt.rna.tf32.f32 %0, %1;" : "=r"(u) : "f"(x));
    return u;
}
__device__ __forceinline__ void cpa16(void* s, const void* g) {
    unsigned sa = (unsigned)__cvta_generic_to_shared(s);
    asm volatile("cp.async.cg.shared.global [%0], [%1], 16;" :: "r"(sa), "l"(g));
}
__device__ __forceinline__ float gelu_f(float x) {
    float x3 = x * x * x;
    return 0.5f * x * (1.f + tanhf(0.7978845608028654f * (x + 0.044715f * x3)));
}

// ============ fp16 tensor-core GEMM: C = A[M,Kd](fp16) @ Bt^T, Bt = [N][Kd] fp16 ============
// BM=128, BK=32, 256 threads = 8 warps (4x2), warp tile 32 x BN/2.
// epi: 0 fp32; 1 gelu->fp16; 2 VFE->fp32+fp16; 3 VFE+final->fp32; 4 fp16; 5 fp32+fp16
template<int BN>
__global__ __launch_bounds__(256, 2)
void gemm_h(const __half* __restrict__ A, const __half* __restrict__ Bt,
            float* __restrict__ C, __half* __restrict__ C16,
            int Kd, int lda, int ldc,
            long long sAo, long long sAi, long long sBo, long long sBi,
            long long sCo, long long sCi, int innerDiv, int causal, int epi,
            const float* __restrict__ bias,
            const float* __restrict__ e_hin,  const float* __restrict__ e_prior,
            const float* __restrict__ e_aux,  const float* __restrict__ e_lr,
            const float* __restrict__ e_res,  const float* __restrict__ e_ln2)
{
    constexpr int BM = 128, LD = 40;          // 32 k + 8 pad halves per row
    constexpr int WN = BN / 2;
    constexpr int NF = BN / 16;
    extern __shared__ __half hsm[];
    __half* sA = hsm;                         // 3 * BM*LD
    __half* sB = hsm + 3 * BM * LD;           // 3 * BN*LD

    int z = blockIdx.z;
    int zo = z / innerDiv, zi = z - zo * innerDiv;
    A  += zo * sAo + zi * sAi;
    Bt += zo * sBo + zi * sBi;
    long long coff = zo * sCo + zi * sCi;

    int tid = threadIdx.x;
    int wid = tid >> 5, lane = tid & 31;
    int wm = wid & 3, wn = wid >> 2;
    int row0 = blockIdx.y * BM, col0 = blockIdx.x * BN;
    int gid = lane >> 2, tig = lane & 3;

    float acc[2][NF][4];
#pragma unroll
    for (int mi = 0; mi < 2; mi++)
#pragma unroll
        for (int ni = 0; ni < NF; ni++)
#pragma unroll
            for (int r = 0; r < 4; r++) acc[mi][ni][r] = 0.f;

    int kTiles = Kd / 32;
    if (causal) { int lim = (row0 + BM) / 32; if (lim < kTiles) kTiles = lim; }

    auto loadTile = [&](int t) {
        int buf = t % 3;
        int k0 = t * 32;
        __half* pA = sA + buf * BM * LD;
        __half* pB = sB + buf * BN * LD;
#pragma unroll
        for (int i = tid; i < BM * 4; i += 256) {
            int m = i >> 2, u = i & 3;
            cpa16(&pA[m * LD + u * 8], A + (size_t)(row0 + m) * lda + k0 + u * 8);
        }
#pragma unroll
        for (int i = tid; i < BN * 4; i += 256) {
            int n = i >> 2, u = i & 3;
            cpa16(&pB[n * LD + u * 8], Bt + (size_t)(col0 + n) * Kd + k0 + u * 8);
        }
        asm volatile("cp.async.commit_group;");
    };

    loadTile(0);
    if (kTiles > 1) loadTile(1);
    else asm volatile("cp.async.commit_group;");

    for (int t = 0; t < kTiles; t++) {
        asm volatile("cp.async.wait_group 1;");
        __syncthreads();
        if (t + 2 < kTiles) loadTile(t + 2);
        else asm volatile("cp.async.commit_group;");
        int buf = t % 3;
        const __half* pA = sA + buf * BM * LD;
        const __half* pB = sB + buf * BN * LD;
#pragma unroll
        for (int ks = 0; ks < 2; ks++) {
            int kb = ks * 16 + 2 * tig;
            uint32_t a[2][4];
#pragma unroll
            for (int mi = 0; mi < 2; mi++) {
                int r = wm * 32 + mi * 16 + gid;
                a[mi][0] = *(const uint32_t*)&pA[r * LD + kb];
                a[mi][1] = *(const uint32_t*)&pA[(r + 8) * LD + kb];
                a[mi][2] = *(const uint32_t*)&pA[r * LD + kb + 8];
                a[mi][3] = *(const uint32_t*)&pA[(r + 8) * LD + kb + 8];
            }
#pragma unroll
            for (int ni = 0; ni < NF; ni++) {
                int n = wn * WN + ni * 8 + gid;
                uint32_t b0 = *(const uint32_t*)&pB[n * LD + kb];
                uint32_t b1 = *(const uint32_t*)&pB[n * LD + kb + 8];
#pragma unroll
                for (int mi = 0; mi < 2; mi++) {
                    asm volatile(
                        "mma.sync.aligned.m16n8k16.row.col.f32.f16.f16.f32 "
                        "{%0,%1,%2,%3}, {%4,%5,%6,%7}, {%8,%9}, {%0,%1,%2,%3};"
                        : "+f"(acc[mi][ni][0]), "+f"(acc[mi][ni][1]),
                          "+f"(acc[mi][ni][2]), "+f"(acc[mi][ni][3])
                        : "r"(a[mi][0]), "r"(a[mi][1]), "r"(a[mi][2]), "r"(a[mi][3]),
                          "r"(b0), "r"(b1));
                }
            }
        }
        __syncthreads();
    }

    float lrv = (epi == 2 || epi == 3) ? e_lr[0] : 0.f;
    bool w32 = (epi == 0 || epi == 2 || epi == 3 || epi == 5);
    bool w16 = (epi == 1 || epi == 2 || epi == 4 || epi == 5);
#pragma unroll
    for (int mi = 0; mi < 2; mi++) {
#pragma unroll
        for (int ni = 0; ni < NF; ni++) {
            int cb = col0 + wn * WN + ni * 8 + 2 * tig;
#pragma unroll
            for (int hf = 0; hf < 2; hf++) {
                int rr = row0 + wm * 32 + mi * 16 + gid + hf * 8;
                float v0 = acc[mi][ni][hf * 2], v1 = acc[mi][ni][hf * 2 + 1];
                long long off = coff + (long long)rr * ldc + cb;
                if (epi == 1) {
                    v0 = gelu_f(v0 + bias[cb]);
                    v1 = gelu_f(v1 + bias[cb + 1]);
                } else if (epi == 2 || epi == 3) {
                    float x0 = v0 + bias[cb], x1 = v1 + bias[cb + 1];
                    float h0 = e_hin[off], h1 = e_hin[off + 1];
                    v0 = h0 + lrv * (x0 - (1e-3f * (h0 - e_prior[off]) + (h0 - e_aux[off])));
                    v1 = h1 + lrv * (x1 - (1e-3f * (h1 - e_prior[off + 1]) + (h1 - e_aux[off + 1])));
                    if (epi == 3) {
                        v0 = e_res[off] + v0 - e_ln2[off];
                        v1 = e_res[off + 1] + v1 - e_ln2[off + 1];
                    }
                }
                if (w32) { float2 f2; f2.x = v0; f2.y = v1; *(float2*)&C[off] = f2; }
                if (w16) { *(__half2*)&C16[off] = __floats2half2_rn(v0, v1); }
            }
        }
    }
}

// ---------------- prep kernels ----------------
// dst[c][r] = fp16(src[r][c] (^2)) ; src R x C fp32 row-major
__global__ void wtr_h_kernel(const float* __restrict__ src, __half* __restrict__ dst,
                             int R, int C, int sq)
{
    __shared__ float t[32][33];
    int bx = blockIdx.x * 32, by = blockIdx.y * 32;
    int x = bx + threadIdx.x;
#pragma unroll
    for (int i = 0; i < 32; i += 8) {
        int y = by + threadIdx.y + i;
        float v = src[(size_t)y * C + x];
        if (sq) v = v * v;
        t[threadIdx.y + i][threadIdx.x] = v;
    }
    __syncthreads();
    int xo = by + threadIdx.x;
#pragma unroll
    for (int i = 0; i < 32; i += 8) {
        int yo = bx + threadIdx.y + i;
        dst[(size_t)yo * R + xo] = __float2half_rn(t[threadIdx.x][threadIdx.y + i]);
    }
}
__global__ void copy_h_kernel(const float* __restrict__ src, __half* __restrict__ dst, int n)
{
    int i = blockIdx.x * 256 + threadIdx.x;
    if (i < n) dst[i] = __float2half_rn(src[i]);
}
// src [b][t(R=1024)][f(C=512)] (row stride srcRow) -> dst fp16 [b][f][t]
__global__ void tr2h_kernel(const float* __restrict__ src, __half* __restrict__ dst,
                            int srcRow, long long sSrcB, long long sDstB)
{
    __shared__ float t[32][33];
    const float* s = src + blockIdx.z * sSrcB;
    __half* d = dst + blockIdx.z * sDstB;
    int f0 = blockIdx.x * 32, t0 = blockIdx.y * 32;
#pragma unroll
    for (int i = 0; i < 32; i += 8)
        t[threadIdx.y + i][threadIdx.x] =
            s[(size_t)(t0 + threadIdx.y + i) * srcRow + f0 + threadIdx.x];
    __syncthreads();
#pragma unroll
    for (int i = 0; i < 32; i += 8)
        d[(size_t)(f0 + threadIdx.y + i) * 1024 + t0 + threadIdx.x] =
            __float2half_rn(t[threadIdx.x][threadIdx.y + i]);
}

// ---------------- layernorm (fp32 out + optional fp16 twin) ----------------
__global__ void ln_kernel(const float* __restrict__ x, const float* __restrict__ gw,
                          const float* __restrict__ bw, float* __restrict__ y,
                          __half* __restrict__ yh)
{
    int bn = blockIdx.x;
    const float* xr = x + (long long)bn * K_;
    int t = threadIdx.x;
    float v0 = xr[t], v1 = xr[t + 256];
    __shared__ float red[8];
    __shared__ float s_mean, s_rstd;
    int lane = t & 31, w = t >> 5;
    float s = warpSum(v0 + v1);
    if (lane == 0) red[w] = s;
    __syncthreads();
    if (t == 0) {
        float tot = 0.f;
        for (int i = 0; i < 8; i++) tot += red[i];
        s_mean = tot * (1.f / 512.f);
    }
    __syncthreads();
    float m = s_mean;
    float d0 = v0 - m, d1 = v1 - m;
    float s2 = warpSum(d0 * d0 + d1 * d1);
    if (lane == 0) red[w] = s2;
    __syncthreads();
    if (t == 0) {
        float tot = 0.f;
        for (int i = 0; i < 8; i++) tot += red[i];
        s_rstd = rsqrtf(tot * (1.f / 512.f) + 1e-5f);
    }
    __syncthreads();
    float r = s_rstd;
    float o0 = d0 * r * gw[t] + bw[t];
    float o1 = d1 * r * gw[t + 256] + bw[t + 256];
    long long base = (long long)bn * K_;
    if (y) { y[base + t] = o0; y[base + t + 256] = o1; }
    if (yh) {
        yh[base + t] = __float2half_rn(o0);
        yh[base + t + 256] = __float2half_rn(o1);
    }
}

// ---------------- transport combines ----------------
__global__ void combine1_kernel(const float* __restrict__ phi, float sign)
{
    int i = blockIdx.x * 256 + threadIdx.x;
    if (i >= BNK_) return;
    int bn = i >> 9, k = i & (K_ - 1);
    const float* pp = phi + bn * 3;
    const float* z = g_Z + (long long)bn * KG_;
    float v = sign * (pp[0] * z[k] + pp[1] * z[K_ + k] + pp[2] * z[2 * K_ + k]);
    g_a1[i] = v;
    h_a1[i] = __float2half_rn(v);
}
__global__ void combine2_kernel(const float* __restrict__ phi, float sign,
                                const float* __restrict__ xbase,
                                const float* __restrict__ resid,
                                float* __restrict__ out32, __half* __restrict__ out16)
{
    int i = blockIdx.x * 256 + threadIdx.x;
    if (i >= BNK_) return;
    int bn = i >> 9, k = i & (K_ - 1);
    const float* pp = phi + bn * 3;
    const float* z = g_Z + (long long)bn * KG_;
    float c = sign * (pp[0] * z[k] + pp[1] * z[K_ + k] + pp[2] * z[2 * K_ + k]);
    float r = xbase[i] + g_a1[i] + 0.5f * c;
    if (resid) r += resid[i];
    if (out32) out32[i] = r;
    if (out16) out16[i] = __float2half_rn(r);
}

// ---------------- fused attention prep + gamma/delta ----------------
__global__ void prep_attn_gamdel_kernel()
{
    int bn = blockIdx.x;
    int b = bn >> 10, n = bn & (N_ - 1);
    int t = threadIdx.x;
    int lane = t & 31;
    __shared__ float sacc[3][H_];
    if (t < 3 * H_) ((float*)sacc)[t] = 0.f;
    __syncthreads();
#pragma unroll
    for (int half = 0; half < 2; half++) {
        int k = t + half * 256;
        long long s2b = (long long)bn * (2 * K_);
        long long qb  = (long long)bn * QKVW_;
        long long ib  = (long long)bn * K_ + k;
        float sqraw = g_s2[s2b + k] + 1e-8f;
        float inv = 1.f / sqraw;
        float q = g_qkv[qb + k];
        g_inv[ib]  = inv;
        g_qinv[ib] = q * inv;
        float sk = g_s2[s2b + K_ + k] + 1e-8f;
        float kv = g_qkv[qb + K_ + k];
        g_e[ib] = sk + kv * kv;
        float qq  = q * q * inv;
        float lsq = logf(sqraw);
        float lsk = logf(sk);
        qq = warpSum(qq); lsq = warpSum(lsq); lsk = warpSum(lsk);
        if (lane == 0) {
            int h = k >> 6;
            atomicAdd(&sacc[0][h], qq);
            atomicAdd(&sacc[1][h], lsq);
            atomicAdd(&sacc[2][h], lsk);
        }
    }
    __syncthreads();
    if (t < H_) {
        int idx = ((b * H_ + t) * N_) + n;
        g_gam[idx] = -0.5f * (sacc[0][t] - (float)DH_ + sacc[1][t]);
        g_del[idx] = 0.5f * sacc[2][t];
    }
}

// ---------------- KL score: tf32 mma, 64x64 tiles ----------------
__global__ __launch_bounds__(256) void score_kernel()
{
    int bh = blockIdx.z;
    int b = bh >> 3, h = bh & 7;
    int i0 = blockIdx.y * 64, j0 = blockIdx.x * 64;
    if (j0 > i0) return;
    constexpr int LDK = 68;
    __shared__ float Qs[64 * LDK];
    __shared__ float Ks[64 * LDK];
    int tid = threadIdx.x;
    int wid = tid >> 5, lane = tid & 31;
    int wm = wid & 3, wn = wid >> 2;
    int lr = lane >> 2, lc = lane & 3;
    int hoff = h * DH_;
    float acc[4][4] = {};
#pragma unroll
    for (int dc = 0; dc < 2; dc++) {
        for (int e = tid; e < 64 * 16; e += 256) {
            int r = e >> 4, c4 = (e & 15) * 4;
            long long qrow = (long long)(b * N_ + i0 + r);
            long long krow = (long long)(b * N_ + j0 + r);
            float4 qv, kv;
            if (dc == 0) {
                qv = *(const float4*)&g_inv[qrow * K_ + hoff + c4];
                qv.x *= -0.5f; qv.y *= -0.5f; qv.z *= -0.5f; qv.w *= -0.5f;
                kv = *(const float4*)&g_e[krow * K_ + hoff + c4];
            } else {
                qv = *(const float4*)&g_qinv[qrow * K_ + hoff + c4];
                kv = *(const float4*)&g_qkv[krow * QKVW_ + K_ + hoff + c4];
            }
            *(float4*)&Qs[r * LDK + c4] = qv;
            *(float4*)&Ks[r * LDK + c4] = kv;
        }
        __syncthreads();
#pragma unroll
        for (int ks = 0; ks < 8; ks++) {
            int kb = ks * 8 + lc;
            int ar = wm * 16 + lr;
            unsigned a0 = f2tf(Qs[ar * LDK + kb]);
            unsigned a1 = f2tf(Qs[(ar + 8) * LDK + kb]);
            unsigned a2 = f2tf(Qs[ar * LDK + kb + 4]);
            unsigned a3 = f2tf(Qs[(ar + 8) * LDK + kb + 4]);
#pragma unroll
            for (int ni = 0; ni < 4; ni++) {
                int bc = wn * 32 + ni * 8 + lr;
                unsigned b0 = f2tf(Ks[bc * LDK + kb]);
                unsigned b1 = f2tf(Ks[bc * LDK + kb + 4]);
                asm volatile(
                    "mma.sync.aligned.m16n8k8.row.col.f32.tf32.tf32.f32 "
                    "{%0,%1,%2,%3}, {%4,%5,%6,%7}, {%8,%9}, {%0,%1,%2,%3};"
                    : "+f"(acc[ni][0]), "+f"(acc[ni][1]),
                      "+f"(acc[ni][2]), "+f"(acc[ni][3])
                    : "r"(a0), "r"(a1), "r"(a2), "r"(a3), "r"(b0), "r"(b1));
            }
        }
        __syncthreads();
    }
    long long gdb = (long long)bh * N_;
#pragma unroll
    for (int half = 0; half < 2; half++) {
        int i = i0 + wm * 16 + lr + half * 8;
        float gv = g_gam[gdb + i];
#pragma unroll
        for (int ni = 0; ni < 4; ni++) {
            int j = j0 + wn * 32 + ni * 8 + 2 * lc;
            float2 o;
            o.x = acc[ni][half * 2 + 0] + gv + g_del[gdb + j];
            o.y = acc[ni][half * 2 + 1] + gv + g_del[gdb + j + 1];
            *(float2*)&g_beta[(gdb + i) * N_ + j] = o;
        }
    }
}

// ---------------- fused softmax + beta_m, outputs fp16 ----------------
__global__ __launch_bounds__(256) void softmax_bm_kernel()
{
    int bi = blockIdx.x;
    int b = bi >> 10, i = bi & (N_ - 1);
    int Jmax = ((i >> 7) + 1) << 7;
    int t = threadIdx.x;
    int lane = t & 31, w = t >> 5;
    __shared__ float red[8];
    __shared__ float s_val;
    float bmacc[4] = {0.f, 0.f, 0.f, 0.f};
    for (int h = 0; h < H_; h++) {
        long long rowoff = (((long long)(b * H_ + h)) * N_ + i) * N_;
        const float* p = g_beta + rowoff;
        __half* ph = h_beta + rowoff;
        float ev[4];
        float m = -1e30f;
#pragma unroll
        for (int jj = 0; jj < 4; jj++) {
            int j = t + jj * 256;
            ev[jj] = (j <= i) ? p[j] : -1e30f;
            m = fmaxf(m, ev[jj]);
        }
        m = warpMax(m);
        if (lane == 0) red[w] = m;
        __syncthreads();
        if (t == 0) {
            float mm = red[0];
            for (int x = 1; x < 8; x++) mm = fmaxf(mm, red[x]);
            s_val = mm;
        }
        __syncthreads();
        m = s_val;
        float s = 0.f;
#pragma unroll
        for (int jj = 0; jj < 4; jj++) {
            ev[jj] = (t + jj * 256 <= i) ? expf(ev[jj] - m) : 0.f;
            s += ev[jj];
        }
        s = warpSum(s);
        if (lane == 0) red[w] = s;
        __syncthreads();
        if (t == 0) {
            float tot = 0.f;
            for (int x = 0; x < 8; x++) tot += red[x];
            s_val = 1.f / tot;
        }
        __syncthreads();
        float inv = s_val;
#pragma unroll
        for (int jj = 0; jj < 4; jj++) {
            int j = t + jj * 256;
            float v = ev[jj] * inv;
            if (j < Jmax) ph[j] = __float2half_rn(v);
            bmacc[jj] += v;
        }
        __syncthreads();
    }
    __half* bm = h_bm + ((long long)b * N_ + i) * N_;
#pragma unroll
    for (int jj = 0; jj < 4; jj++) {
        int j = t + jj * 256;
        if (j < Jmax) bm[j] = __float2half_rn(bmacc[jj] * 0.125f);
    }
}

// ---------------- host ----------------
#define SM128 (3 * (128 * 40 + 128 * 40) * 2)   // 61440
#define SM64  (3 * (128 * 40 + 64 * 40) * 2)    // 46080
static inline void launch_gh(const __half* A, const __half* Bt, float* C, __half* C16,
                             int M, int Ncols, int Kd, int lda, int ldc,
                             long long sAo, long long sAi, long long sBo, long long sBi,
                             long long sCo, long long sCi, int innerDiv, int batch,
                             int causal, int epi,
                             const float* bias = nullptr,
                             const float* e_hin = nullptr, const float* e_prior = nullptr,
                             const float* e_aux = nullptr, const float* e_lr = nullptr,
                             const float* e_res = nullptr, const float* e_ln2 = nullptr)
{
    if (Ncols % 128 == 0) {
        dim3 g(Ncols / 128, M / 128, batch);
        gemm_h<128><<<g, 256, SM128>>>(A, Bt, C, C16, Kd, lda, ldc,
                                       sAo, sAi, sBo, sBi, sCo, sCi, innerDiv, causal, epi,
                                       bias, e_hin, e_prior, e_aux, e_lr, e_res, e_ln2);
    } else {
        dim3 g(Ncols / 64, M / 128, batch);
        gemm_h<64><<<g, 256, SM64>>>(A, Bt, C, C16, Kd, lda, ldc,
                                     sAo, sAi, sBo, sBi, sCo, sCi, innerDiv, causal, epi,
                                     bias, e_hin, e_prior, e_aux, e_lr, e_res, e_ln2);
    }
}

extern "C" void kernel_launch(void* const* d_in, const int* in_sizes, int n_in,
                              void* d_out, int out_size)
{
    const float* mu_q     = (const float*)d_in[0];
    const float* sigma_q  = (const float*)d_in[1];
    const float* phi      = (const float*)d_in[2];
    const float* gen      = (const float*)d_in[3];
    const float* mu_prior = (const float*)d_in[5];
    const float* Wq  = (const float*)d_in[6];
    const float* Wk  = (const float*)d_in[7];
    const float* Wv  = (const float*)d_in[8];
    const float* Wo  = (const float*)d_in[9];
    const float* g1  = (const float*)d_in[10];
    const float* be1 = (const float*)d_in[11];
    const float* g2  = (const float*)d_in[12];
    const float* be2 = (const float*)d_in[13];
    const float* W1  = (const float*)d_in[14];
    const float* bh1 = (const float*)d_in[15];
    const float* W2  = (const float*)d_in[16];
    const float* bh2 = (const float*)d_in[17];
    const float* lr  = (const float*)d_in[18];

    static int attrDone = 0;
    if (!attrDone) {
        cudaFuncSetAttribute(gemm_h<128>, cudaFuncAttributeMaxDynamicSharedMemorySize, SM128);
        cudaFuncSetAttribute(gemm_h<64>,  cudaFuncAttributeMaxDynamicSharedMemorySize, SM64);
        attrDone = 1;
    }

    void* tp;
#define GETSYMF(var, sym) cudaGetSymbolAddress(&tp, sym); float* var = (float*)tp
#define GETSYMH(var, sym) cudaGetSymbolAddress(&tp, sym); __half* var = (__half*)tp
    GETSYMH(ph_gcatT, h_gcatT); GETSYMH(ph_wqkvT, h_wqkvT); GETSYMH(ph_w2qkT, h_w2qkT);
    GETSYMH(ph_WoT, h_WoT);     GETSYMH(ph_W1T, h_W1T);     GETSYMH(ph_W2T, h_W2T);
    GETSYMH(ph_sig, h_sig);     GETSYMH(ph_ln1, h_ln1);     GETSYMH(ph_a1, h_a1);
    GETSYMH(ph_mug, h_mug);     GETSYMH(ph_attn, h_attn);   GETSYMH(ph_o, h_o);
    GETSYMH(ph_ln2, h_ln2);     GETSYMH(ph_hh, h_hh);       GETSYMH(ph_hid, h_hid);
    GETSYMH(ph_beta, h_beta);   GETSYMH(ph_bm, h_bm);       GETSYMH(ph_vT, h_vT);
    GETSYMH(ph_ln2T, h_ln2T);   GETSYMH(ph_hT, h_hT);
    GETSYMF(pg_ln1, g_ln1);     GETSYMF(pg_Z, g_Z);         GETSYMF(pg_qkv, g_qkv);
    GETSYMF(pg_s2, g_s2);       GETSYMF(pg_o, g_o);         GETSYMF(pg_res, g_res);
    GETSYMF(pg_ln2, g_ln2);     GETSYMF(pg_h, g_h);         GETSYMF(pg_bh, g_bh);
#undef GETSYMF
#undef GETSYMH

    const int EW = 256;
    const int GB_BNK = BNK_ / EW;
    dim3 tb(32, 8);

    // ---- prep: weights -> fp16 transposed; gen/sigma -> fp16 ----
    copy_h_kernel<<<(KG_ * K_ + EW - 1) / EW, EW>>>(gen, ph_gcatT, KG_ * K_);
    copy_h_kernel<<<(BNK_ + EW - 1) / EW, EW>>>(sigma_q, ph_sig, BNK_);
    wtr_h_kernel<<<dim3(16, 16), tb>>>(Wq, ph_wqkvT, K_, K_, 0);
    wtr_h_kernel<<<dim3(16, 16), tb>>>(Wk, ph_wqkvT + K_ * K_, K_, K_, 0);
    wtr_h_kernel<<<dim3(16, 16), tb>>>(Wv, ph_wqkvT + 2 * K_ * K_, K_, K_, 0);
    wtr_h_kernel<<<dim3(16, 16), tb>>>(Wq, ph_w2qkT, K_, K_, 1);
    wtr_h_kernel<<<dim3(16, 16), tb>>>(Wk, ph_w2qkT + K_ * K_, K_, K_, 1);
    wtr_h_kernel<<<dim3(16, 16), tb>>>(Wo, ph_WoT, K_, K_, 0);
    wtr_h_kernel<<<dim3(64, 16), tb>>>(W1, ph_W1T, K_, HID_, 0);
    wtr_h_kernel<<<dim3(16, 64), tb>>>(W2, ph_W2T, HID_, K_, 0);

    // ---- attention sublayer ----
    ln_kernel<<<BN_, 256>>>(mu_q, g1, be1, pg_ln1, ph_ln1);
    launch_gh(ph_ln1, ph_gcatT, pg_Z, nullptr, BN_, KG_, K_, K_, KG_,
              0,0,0,0,0,0, 1, 1, 0, 0);
    combine1_kernel<<<GB_BNK, EW>>>(phi, 1.f);
    launch_gh(ph_a1, ph_gcatT, pg_Z, nullptr, BN_, KG_, K_, K_, KG_,
              0,0,0,0,0,0, 1, 1, 0, 0);
    combine2_kernel<<<GB_BNK, EW>>>(phi, 1.f, pg_ln1, nullptr, nullptr, ph_mug);

    launch_gh(ph_mug, ph_wqkvT, pg_qkv, nullptr, BN_, QKVW_, K_, K_, QKVW_,
              0,0,0,0,0,0, 1, 1, 0, 0);
    launch_gh(ph_sig, ph_w2qkT, pg_s2, nullptr, BN_, 2 * K_, K_, K_, 2 * K_,
              0,0,0,0,0,0, 1, 1, 0, 0);

    prep_attn_gamdel_kernel<<<BN_, 256>>>();
    // vT fp16 (v = cols [1024,1536) of qkv)
    tr2h_kernel<<<dim3(16, 32, B_), tb>>>(pg_qkv + 2 * K_, ph_vT, QKVW_,
                                          (long long)N_ * QKVW_, (long long)K_ * N_);
    score_kernel<<<dim3(N_ / 64, N_ / 64, B_ * H_), 256>>>();
    softmax_bm_kernel<<<BN_, 256>>>();

    // attn = beta @ v (batched b,h; causal) -> fp16 only
    launch_gh(ph_beta, ph_vT, nullptr, ph_attn, N_, DH_, N_, N_, K_,
              8LL * NN_, (long long)NN_,
              (long long)K_ * N_, 64LL * N_,
              (long long)N_ * K_, 64, H_, B_ * H_, 1, 4);

    launch_gh(ph_attn, ph_WoT, pg_o, ph_o, BN_, K_, K_, K_, K_,
              0,0,0,0,0,0, 1, 1, 0, 5);
    launch_gh(ph_o, ph_gcatT, pg_Z, nullptr, BN_, KG_, K_, K_, KG_,
              0,0,0,0,0,0, 1, 1, 0, 0);
    combine1_kernel<<<GB_BNK, EW>>>(phi, -1.f);
    launch_gh(ph_a1, ph_gcatT, pg_Z, nullptr, BN_, KG_, K_, K_, KG_,
              0,0,0,0,0,0, 1, 1, 0, 0);
    combine2_kernel<<<GB_BNK, EW>>>(phi, -1.f, pg_o, mu_q, pg_res, nullptr);

    // ---- FFN sublayer ----
    ln_kernel<<<BN_, 256>>>(pg_res, g2, be2, pg_ln2, ph_ln2);
    tr2h_kernel<<<dim3(16, 32, B_), tb>>>(pg_ln2, ph_ln2T, K_,
                                          (long long)N_ * K_, (long long)K_ * N_);
    float* out = (float*)d_out;

    // iteration 1
    launch_gh(ph_bm, ph_ln2T, pg_bh, nullptr, N_, K_, N_, N_, K_,
              (long long)NN_, 0, (long long)K_ * N_, 0, (long long)N_ * K_, 0,
              1, B_, 1, 0);
    launch_gh(ph_ln2, ph_W1T, nullptr, ph_hid, BN_, HID_, K_, K_, HID_,
              0,0,0,0,0,0, 1, 1, 0, 1, bh1);
    launch_gh(ph_hid, ph_W2T, pg_h, ph_hh, BN_, K_, HID_, HID_, K_,
              0,0,0,0,0,0, 1, 1, 0, 2, bh2, pg_ln2, mu_prior, pg_bh, lr);

    // iteration 2 (final residual fused -> out)
    tr2h_kernel<<<dim3(16, 32, B_), tb>>>(pg_h, ph_hT, K_,
                                          (long long)N_ * K_, (long long)K_ * N_);
    launch_gh(ph_bm, ph_hT, pg_bh, nullptr, N_, K_, N_, N_, K_,
              (long long)NN_, 0, (long long)K_ * N_, 0, (long long)N_ * K_, 0,
              1, B_, 1, 0);
    launch_gh(ph_hh, ph_W1T, nullptr, ph_hid, BN_, HID_, K_, K_, HID_,
              0,0,0,0,0,0, 1, 1, 0, 1, bh1);
    launch_gh(ph_hid, ph_W2T, out, nullptr, BN_, K_, HID_, HID_, K_,
              0,0,0,0,0,0, 1, 1, 0, 3, bh2, pg_h, mu_prior, pg_bh, lr, pg_res, pg_ln2);

    // ---- remaining outputs ----
    cudaMemcpyAsync(out + BNK_, sigma_q, (size_t)BNK_ * sizeof(float),
                    cudaMemcpyDeviceToDevice);
    cudaMemcpyAsync(out + 2 * (size_t)BNK_, phi, (size_t)B_ * N_ * 3 * sizeof(float),
                    cudaMemcpyDeviceToDevice);
}

// round 9
// speedup vs baseline: 1.7513x; 1.0856x over previous
#include <cuda_runtime.h>
#include <cuda_fp16.h>
#include <math.h>
#include <stdint.h>

#define B_   4
#define N_   1024
#define K_   512
#define H_   8
#define DH_  64
#define HID_ 2048
#define KG_  (3*K_)
#define BN_  (B_*N_)
#define BNK_ (B_*N_*K_)
#define BHN_ (B_*H_*N_)
#define NN_  (N_*N_)
#define QKVW_ (3*K_)

// ---------------- device scratch ----------------
__device__ __half h_gcatT[KG_*K_];
__device__ __half h_wqkvT[QKVW_*K_];
__device__ __half h_w2qkT[2*K_*K_];
__device__ __half h_WoT[K_*K_];
__device__ __half h_W1T[HID_*K_];
__device__ __half h_W2T[K_*HID_];
__device__ __half h_sig[BNK_];
__device__ __half h_ln1[BNK_];
__device__ __half h_a1[BNK_];
__device__ __half h_mug[BNK_];
__device__ __half h_attn[BNK_];
__device__ __half h_ln2[BNK_];
__device__ __half h_hh[BNK_];
__device__ __half h_hid[BN_*HID_];
__device__ __half h_beta[33554432];
__device__ __half h_bm[B_*NN_];
__device__ __half h_vT[BNK_];
__device__ __half h_ln2T[BNK_];
__device__ __half h_hT[BNK_];
__device__ __half h_Z[BN_*KG_];
__device__ __half h_Qe[BHN_*2*DH_];
__device__ __half h_Ke[BHN_*2*DH_];
__device__ __half h_o[BNK_];
__device__ float g_ln1[BNK_];
__device__ float g_qkv[BN_*QKVW_];
__device__ float g_s2[BN_*2*K_];
__device__ float g_gam[BHN_];
__device__ float g_del[BHN_];
__device__ float g_beta[33554432];
__device__ float g_o[BNK_];
__device__ float g_res[BNK_];
__device__ float g_ln2[BNK_];
__device__ float g_h[BNK_];
__device__ float g_bh[BNK_];

// ---------------- helpers ----------------
__device__ __forceinline__ float warpSum(float v) {
#pragma unroll
    for (int o = 16; o; o >>= 1) v += __shfl_down_sync(0xffffffffu, v, o);
    return v;
}
__device__ __forceinline__ float allMax(float v) {
#pragma unroll
    for (int o = 16; o; o >>= 1) v = fmaxf(v, __shfl_xor_sync(0xffffffffu, v, o));
    return v;
}
__device__ __forceinline__ float allSum(float v) {
#pragma unroll
    for (int o = 16; o; o >>= 1) v += __shfl_xor_sync(0xffffffffu, v, o);
    return v;
}
__device__ __forceinline__ void cpa16(void* s, const void* g) {
    unsigned sa = (unsigned)__cvta_generic_to_shared(s);
    asm volatile("cp.async.cg.shared.global [%0], [%1], 16;" :: "r"(sa), "l"(g));
}
__device__ __forceinline__ float gelu_f(float x) {
    float x3 = x * x * x;
    return 0.5f * x * (1.f + tanhf(0.7978845608028654f * (x + 0.044715f * x3)));
}

// ============ fp16 tensor-core GEMM: C = A[M,Kd](fp16) @ Bt^T, Bt = [N][Kd] fp16 ============
// epi: 0 fp32; 1 gelu->fp16; 2 VFE->fp32+fp16; 3 VFE+final->fp32; 4 fp16; 5 fp32+fp16
template<int BN>
__global__ __launch_bounds__(256, 2)
void gemm_h(const __half* __restrict__ A, const __half* __restrict__ Bt,
            float* __restrict__ C, __half* __restrict__ C16,
            int Kd, int lda, int ldc,
            long long sAo, long long sAi, long long sBo, long long sBi,
            long long sCo, long long sCi, int innerDiv, int causal, int epi,
            const float* __restrict__ bias,
            const float* __restrict__ e_hin,  const float* __restrict__ e_prior,
            const float* __restrict__ e_aux,  const float* __restrict__ e_lr,
            const float* __restrict__ e_res,  const float* __restrict__ e_ln2)
{
    constexpr int BM = 128, LD = 40;
    constexpr int WN = BN / 2;
    constexpr int NF = BN / 16;
    extern __shared__ __half hsm[];
    __half* sA = hsm;
    __half* sB = hsm + 3 * BM * LD;

    int z = blockIdx.z;
    int zo = z / innerDiv, zi = z - zo * innerDiv;
    A  += zo * sAo + zi * sAi;
    Bt += zo * sBo + zi * sBi;
    long long coff = zo * sCo + zi * sCi;

    int tid = threadIdx.x;
    int wid = tid >> 5, lane = tid & 31;
    int wm = wid & 3, wn = wid >> 2;
    int row0 = blockIdx.y * BM, col0 = blockIdx.x * BN;
    int gid = lane >> 2, tig = lane & 3;

    float acc[2][NF][4];
#pragma unroll
    for (int mi = 0; mi < 2; mi++)
#pragma unroll
        for (int ni = 0; ni < NF; ni++)
#pragma unroll
            for (int r = 0; r < 4; r++) acc[mi][ni][r] = 0.f;

    int kTiles = Kd / 32;
    if (causal) { int lim = (row0 + BM) / 32; if (lim < kTiles) kTiles = lim; }

    auto loadTile = [&](int t) {
        int buf = t % 3;
        int k0 = t * 32;
        __half* pA = sA + buf * BM * LD;
        __half* pB = sB + buf * BN * LD;
#pragma unroll
        for (int i = tid; i < BM * 4; i += 256) {
            int m = i >> 2, u = i & 3;
            cpa16(&pA[m * LD + u * 8], A + (size_t)(row0 + m) * lda + k0 + u * 8);
        }
#pragma unroll
        for (int i = tid; i < BN * 4; i += 256) {
            int n = i >> 2, u = i & 3;
            cpa16(&pB[n * LD + u * 8], Bt + (size_t)(col0 + n) * Kd + k0 + u * 8);
        }
        asm volatile("cp.async.commit_group;");
    };

    loadTile(0);
    if (kTiles > 1) loadTile(1);
    else asm volatile("cp.async.commit_group;");

    for (int t = 0; t < kTiles; t++) {
        asm volatile("cp.async.wait_group 1;");
        __syncthreads();
        if (t + 2 < kTiles) loadTile(t + 2);
        else asm volatile("cp.async.commit_group;");
        int buf = t % 3;
        const __half* pA = sA + buf * BM * LD;
        const __half* pB = sB + buf * BN * LD;
#pragma unroll
        for (int ks = 0; ks < 2; ks++) {
            int kb = ks * 16 + 2 * tig;
            uint32_t a[2][4];
#pragma unroll
            for (int mi = 0; mi < 2; mi++) {
                int r = wm * 32 + mi * 16 + gid;
                a[mi][0] = *(const uint32_t*)&pA[r * LD + kb];
                a[mi][1] = *(const uint32_t*)&pA[(r + 8) * LD + kb];
                a[mi][2] = *(const uint32_t*)&pA[r * LD + kb + 8];
                a[mi][3] = *(const uint32_t*)&pA[(r + 8) * LD + kb + 8];
            }
#pragma unroll
            for (int ni = 0; ni < NF; ni++) {
                int n = wn * WN + ni * 8 + gid;
                uint32_t b0 = *(const uint32_t*)&pB[n * LD + kb];
                uint32_t b1 = *(const uint32_t*)&pB[n * LD + kb + 8];
#pragma unroll
                for (int mi = 0; mi < 2; mi++) {
                    asm volatile(
                        "mma.sync.aligned.m16n8k16.row.col.f32.f16.f16.f32 "
                        "{%0,%1,%2,%3}, {%4,%5,%6,%7}, {%8,%9}, {%0,%1,%2,%3};"
                        : "+f"(acc[mi][ni][0]), "+f"(acc[mi][ni][1]),
                          "+f"(acc[mi][ni][2]), "+f"(acc[mi][ni][3])
                        : "r"(a[mi][0]), "r"(a[mi][1]), "r"(a[mi][2]), "r"(a[mi][3]),
                          "r"(b0), "r"(b1));
                }
            }
        }
        __syncthreads();
    }

    float lrv = (epi == 2 || epi == 3) ? e_lr[0] : 0.f;
    bool w32 = (epi == 0 || epi == 2 || epi == 3 || epi == 5);
    bool w16 = (epi == 1 || epi == 2 || epi == 4 || epi == 5);
#pragma unroll
    for (int mi = 0; mi < 2; mi++) {
#pragma unroll
        for (int ni = 0; ni < NF; ni++) {
            int cb = col0 + wn * WN + ni * 8 + 2 * tig;
#pragma unroll
            for (int hf = 0; hf < 2; hf++) {
                int rr = row0 + wm * 32 + mi * 16 + gid + hf * 8;
                float v0 = acc[mi][ni][hf * 2], v1 = acc[mi][ni][hf * 2 + 1];
                long long off = coff + (long long)rr * ldc + cb;
                if (epi == 1) {
                    v0 = gelu_f(v0 + bias[cb]);
                    v1 = gelu_f(v1 + bias[cb + 1]);
                } else if (epi == 2 || epi == 3) {
                    float x0 = v0 + bias[cb], x1 = v1 + bias[cb + 1];
                    float h0 = e_hin[off], h1 = e_hin[off + 1];
                    v0 = h0 + lrv * (x0 - (1e-3f * (h0 - e_prior[off]) + (h0 - e_aux[off])));
                    v1 = h1 + lrv * (x1 - (1e-3f * (h1 - e_prior[off + 1]) + (h1 - e_aux[off + 1])));
                    if (epi == 3) {
                        v0 = e_res[off] + v0 - e_ln2[off];
                        v1 = e_res[off + 1] + v1 - e_ln2[off + 1];
                    }
                }
                if (w32) { float2 f2; f2.x = v0; f2.y = v1; *(float2*)&C[off] = f2; }
                if (w16) { *(__half2*)&C16[off] = __floats2half2_rn(v0, v1); }
            }
        }
    }
}

// ---------------- prep kernels ----------------
__global__ void wtr_h_kernel(const float* __restrict__ src, __half* __restrict__ dst,
                             int R, int C, int sq)
{
    __shared__ float t[32][33];
    int bx = blockIdx.x * 32, by = blockIdx.y * 32;
    int x = bx + threadIdx.x;
#pragma unroll
    for (int i = 0; i < 32; i += 8) {
        int y = by + threadIdx.y + i;
        float v = src[(size_t)y * C + x];
        if (sq) v = v * v;
        t[threadIdx.y + i][threadIdx.x] = v;
    }
    __syncthreads();
    int xo = by + threadIdx.x;
#pragma unroll
    for (int i = 0; i < 32; i += 8) {
        int yo = bx + threadIdx.y + i;
        dst[(size_t)yo * R + xo] = __float2half_rn(t[threadIdx.x][threadIdx.y + i]);
    }
}
__global__ void copy_h_kernel(const float* __restrict__ src, __half* __restrict__ dst, int n)
{
    int i = blockIdx.x * 256 + threadIdx.x;
    if (i < n) dst[i] = __float2half_rn(src[i]);
}
__global__ void tr2h_kernel(const float* __restrict__ src, __half* __restrict__ dst,
                            int srcRow, long long sSrcB, long long sDstB)
{
    __shared__ float t[32][33];
    const float* s = src + blockIdx.z * sSrcB;
    __half* d = dst + blockIdx.z * sDstB;
    int f0 = blockIdx.x * 32, t0 = blockIdx.y * 32;
#pragma unroll
    for (int i = 0; i < 32; i += 8)
        t[threadIdx.y + i][threadIdx.x] =
            s[(size_t)(t0 + threadIdx.y + i) * srcRow + f0 + threadIdx.x];
    __syncthreads();
#pragma unroll
    for (int i = 0; i < 32; i += 8)
        d[(size_t)(f0 + threadIdx.y + i) * 1024 + t0 + threadIdx.x] =
            __float2half_rn(t[threadIdx.x][threadIdx.y + i]);
}

// ---------------- layernorm (fp32 out + fp16 twin) ----------------
__global__ void ln_kernel(const float* __restrict__ x, const float* __restrict__ gw,
                          const float* __restrict__ bw, float* __restrict__ y,
                          __half* __restrict__ yh)
{
    int bn = blockIdx.x;
    const float* xr = x + (long long)bn * K_;
    int t = threadIdx.x;
    float v0 = xr[t], v1 = xr[t + 256];
    __shared__ float red[8];
    __shared__ float s_mean, s_rstd;
    int lane = t & 31, w = t >> 5;
    float s = warpSum(v0 + v1);
    if (lane == 0) red[w] = s;
    __syncthreads();
    if (t == 0) {
        float tot = 0.f;
        for (int i = 0; i < 8; i++) tot += red[i];
        s_mean = tot * (1.f / 512.f);
    }
    __syncthreads();
    float m = s_mean;
    float d0 = v0 - m, d1 = v1 - m;
    float s2 = warpSum(d0 * d0 + d1 * d1);
    if (lane == 0) red[w] = s2;
    __syncthreads();
    if (t == 0) {
        float tot = 0.f;
        for (int i = 0; i < 8; i++) tot += red[i];
        s_rstd = rsqrtf(tot * (1.f / 512.f) + 1e-5f);
    }
    __syncthreads();
    float r = s_rstd;
    float o0 = d0 * r * gw[t] + bw[t];
    float o1 = d1 * r * gw[t + 256] + bw[t + 256];
    long long base = (long long)bn * K_;
    if (y) { y[base + t] = o0; y[base + t + 256] = o1; }
    if (yh) {
        yh[base + t] = __float2half_rn(o0);
        yh[base + t + 256] = __float2half_rn(o1);
    }
}

// ---------------- transport combines (fp16 Z) ----------------
__global__ void combine1_kernel(const float* __restrict__ phi, float sign)
{
    int i = blockIdx.x * 256 + threadIdx.x;
    if (i >= BNK_) return;
    int bn = i >> 9, k = i & (K_ - 1);
    const float* pp = phi + bn * 3;
    const __half* z = h_Z + (long long)bn * KG_;
    float v = sign * (pp[0] * __half2float(z[k]) + pp[1] * __half2float(z[K_ + k])
                    + pp[2] * __half2float(z[2 * K_ + k]));
    h_a1[i] = __float2half_rn(v);
}
__global__ void combine2_kernel(const float* __restrict__ phi, float sign,
                                const float* __restrict__ xbase,
                                const float* __restrict__ resid,
                                float* __restrict__ out32, __half* __restrict__ out16)
{
    int i = blockIdx.x * 256 + threadIdx.x;
    if (i >= BNK_) return;
    int bn = i >> 9, k = i & (K_ - 1);
    const float* pp = phi + bn * 3;
    const __half* z = h_Z + (long long)bn * KG_;
    float c = sign * (pp[0] * __half2float(z[k]) + pp[1] * __half2float(z[K_ + k])
                    + pp[2] * __half2float(z[2 * K_ + k]));
    float r = xbase[i] + __half2float(h_a1[i]) + 0.5f * c;
    if (resid) r += resid[i];
    if (out32) out32[i] = r;
    if (out16) out16[i] = __float2half_rn(r);
}

// ---------------- fused attention prep -> fp16 Qe/Ke + gamma/delta ----------------
__global__ void prep_attn_gamdel_kernel()
{
    int bn = blockIdx.x;
    int b = bn >> 10, n = bn & (N_ - 1);
    int t = threadIdx.x;
    int lane = t & 31;
    __shared__ float sacc[3][H_];
    if (t < 3 * H_) ((float*)sacc)[t] = 0.f;
    __syncthreads();
#pragma unroll
    for (int half = 0; half < 2; half++) {
        int k = t + half * 256;
        long long s2b = (long long)bn * (2 * K_);
        long long qb  = (long long)bn * QKVW_;
        float sqraw = g_s2[s2b + k] + 1e-8f;
        float inv = 1.f / sqraw;
        float q = g_qkv[qb + k];
        float sk = g_s2[s2b + K_ + k] + 1e-8f;
        float kv = g_qkv[qb + K_ + k];
        int h = k >> 6, d = k & 63;
        size_t qe = (((size_t)(b * H_ + h)) * N_ + n) * 128 + d;
        h_Qe[qe]      = __float2half_rn(-0.5f * inv);
        h_Qe[qe + 64] = __float2half_rn(q * inv);
        h_Ke[qe]      = __float2half_rn(sk + kv * kv);
        h_Ke[qe + 64] = __float2half_rn(kv);
        float qq  = q * q * inv;
        float lsq = logf(sqraw);
        float lsk = logf(sk);
        qq = warpSum(qq); lsq = warpSum(lsq); lsk = warpSum(lsk);
        if (lane == 0) {
            atomicAdd(&sacc[0][h], qq);
            atomicAdd(&sacc[1][h], lsq);
            atomicAdd(&sacc[2][h], lsk);
        }
    }
    __syncthreads();
    if (t < H_) {
        int idx = ((b * H_ + t) * N_) + n;
        g_gam[idx] = -0.5f * (sacc[0][t] - (float)DH_ + sacc[1][t]);
        g_del[idx] = 0.5f * sacc[2][t];
    }
}

// ---------------- KL score: fp16 mma, 64x64 tiles, K=128 ----------------
__global__ __launch_bounds__(256) void score_kernel()
{
    int bh = blockIdx.z;
    int i0 = blockIdx.y * 64, j0 = blockIdx.x * 64;
    if (j0 > i0) return;
    constexpr int LD = 136;
    __shared__ __half Qs[64 * LD];
    __shared__ __half Ks[64 * LD];
    int tid = threadIdx.x;
    int wid = tid >> 5, lane = tid & 31;
    int wm = wid & 3, wn = wid >> 2;
    int gid = lane >> 2, tig = lane & 3;

    const __half* Qsrc = h_Qe + (((size_t)bh) * N_ + i0) * 128;
    const __half* Ksrc = h_Ke + (((size_t)bh) * N_ + j0) * 128;
    // 64 rows x 16 chunks of 8 halves: load BOTH Q and K per (r,u)
    for (int i = tid; i < 1024; i += 256) {
        int r = i >> 4, u = (i & 15) * 8;
        cpa16(&Qs[r * LD + u], Qsrc + (size_t)r * 128 + u);
        cpa16(&Ks[r * LD + u], Ksrc + (size_t)r * 128 + u);
    }
    asm volatile("cp.async.commit_group;");
    asm volatile("cp.async.wait_group 0;");
    __syncthreads();

    float acc[4][4] = {};
#pragma unroll
    for (int ks = 0; ks < 8; ks++) {
        int kb = ks * 16 + 2 * tig;
        int ar = wm * 16 + gid;
        uint32_t a0 = *(const uint32_t*)&Qs[ar * LD + kb];
        uint32_t a1 = *(const uint32_t*)&Qs[(ar + 8) * LD + kb];
        uint32_t a2 = *(const uint32_t*)&Qs[ar * LD + kb + 8];
        uint32_t a3 = *(const uint32_t*)&Qs[(ar + 8) * LD + kb + 8];
#pragma unroll
        for (int ni = 0; ni < 4; ni++) {
            int n = wn * 32 + ni * 8 + gid;
            uint32_t b0 = *(const uint32_t*)&Ks[n * LD + kb];
            uint32_t b1 = *(const uint32_t*)&Ks[n * LD + kb + 8];
            asm volatile(
                "mma.sync.aligned.m16n8k16.row.col.f32.f16.f16.f32 "
                "{%0,%1,%2,%3}, {%4,%5,%6,%7}, {%8,%9}, {%0,%1,%2,%3};"
                : "+f"(acc[ni][0]), "+f"(acc[ni][1]),
                  "+f"(acc[ni][2]), "+f"(acc[ni][3])
                : "r"(a0), "r"(a1), "r"(a2), "r"(a3), "r"(b0), "r"(b1));
        }
    }

    long long gdb = (long long)bh * N_;
#pragma unroll
    for (int hf = 0; hf < 2; hf++) {
        int i = i0 + wm * 16 + gid + hf * 8;
        float gv = g_gam[gdb + i];
#pragma unroll
        for (int ni = 0; ni < 4; ni++) {
            int j = j0 + wn * 32 + ni * 8 + 2 * tig;
            float2 o;
            o.x = acc[ni][hf * 2 + 0] + gv + g_del[gdb + j];
            o.y = acc[ni][hf * 2 + 1] + gv + g_del[gdb + j + 1];
            *(float2*)&g_beta[(gdb + i) * N_ + j] = o;
        }
    }
}

// ---------------- softmax: 1 warp per (head,row) + fused beta_m ----------------
__global__ __launch_bounds__(256) void softmax_bm_kernel()
{
    int bi = blockIdx.x;
    int b = bi >> 10, i = bi & (N_ - 1);
    int Jmax = ((i >> 7) + 1) << 7;
    int tid = threadIdx.x;
    int w = tid >> 5, lane = tid & 31;
    __shared__ float bmbuf[H_][N_];   // 32 KB

    long long rowoff = (((long long)(b * H_ + w)) * N_ + i) * N_;
    const float* p = g_beta + rowoff;
    __half* ph = h_beta + rowoff;

    float ev[32];
    float m = -1e30f;
#pragma unroll
    for (int jj = 0; jj < 32; jj++) {
        int j = lane + jj * 32;
        float v = (j <= i) ? p[j] : -1e30f;
        ev[jj] = v;
        m = fmaxf(m, v);
    }
    m = allMax(m);
    float s = 0.f;
#pragma unroll
    for (int jj = 0; jj < 32; jj++) {
        ev[jj] = (lane + jj * 32 <= i) ? expf(ev[jj] - m) : 0.f;
        s += ev[jj];
    }
    s = allSum(s);
    float inv = 1.f / s;
#pragma unroll
    for (int jj = 0; jj < 32; jj++) {
        int j = lane + jj * 32;
        if (j < Jmax) {
            float v = ev[jj] * inv;
            ph[j] = __float2half_rn(v);
            bmbuf[w][j] = v;
        }
    }
    __syncthreads();
    __half* bm = h_bm + ((long long)b * N_ + i) * N_;
    for (int j = tid; j < Jmax; j += 256) {
        float t = 0.f;
#pragma unroll
        for (int h = 0; h < H_; h++) t += bmbuf[h][j];
        bm[j] = __float2half_rn(t * 0.125f);
    }
}

// ---------------- host ----------------
#define SM128 (3 * (128 * 40 + 128 * 40) * 2)   // 61440
#define SM64  (3 * (128 * 40 + 64 * 40) * 2)    // 46080
static inline void launch_gh(const __half* A, const __half* Bt, float* C, __half* C16,
                             int M, int Ncols, int Kd, int lda, int ldc,
                             long long sAo, long long sAi, long long sBo, long long sBi,
                             long long sCo, long long sCi, int innerDiv, int batch,
                             int causal, int epi,
                             const float* bias = nullptr,
                             const float* e_hin = nullptr, const float* e_prior = nullptr,
                             const float* e_aux = nullptr, const float* e_lr = nullptr,
                             const float* e_res = nullptr, const float* e_ln2 = nullptr)
{
    if (Ncols % 128 == 0) {
        dim3 g(Ncols / 128, M / 128, batch);
        gemm_h<128><<<g, 256, SM128>>>(A, Bt, C, C16, Kd, lda, ldc,
                                       sAo, sAi, sBo, sBi, sCo, sCi, innerDiv, causal, epi,
                                       bias, e_hin, e_prior, e_aux, e_lr, e_res, e_ln2);
    } else {
        dim3 g(Ncols / 64, M / 128, batch);
        gemm_h<64><<<g, 256, SM64>>>(A, Bt, C, C16, Kd, lda, ldc,
                                     sAo, sAi, sBo, sBi, sCo, sCi, innerDiv, causal, epi,
                                     bias, e_hin, e_prior, e_aux, e_lr, e_res, e_ln2);
    }
}

extern "C" void kernel_launch(void* const* d_in, const int* in_sizes, int n_in,
                              void* d_out, int out_size)
{
    const float* mu_q     = (const float*)d_in[0];
    const float* sigma_q  = (const float*)d_in[1];
    const float* phi      = (const float*)d_in[2];
    const float* gen      = (const float*)d_in[3];
    const float* mu_prior = (const float*)d_in[5];
    const float* Wq  = (const float*)d_in[6];
    const float* Wk  = (const float*)d_in[7];
    const float* Wv  = (const float*)d_in[8];
    const float* Wo  = (const float*)d_in[9];
    const float* g1  = (const float*)d_in[10];
    const float* be1 = (const float*)d_in[11];
    const float* g2  = (const float*)d_in[12];
    const float* be2 = (const float*)d_in[13];
    const float* W1  = (const float*)d_in[14];
    const float* bh1 = (const float*)d_in[15];
    const float* W2  = (const float*)d_in[16];
    const float* bh2 = (const float*)d_in[17];
    const float* lr  = (const float*)d_in[18];

    static int attrDone = 0;
    if (!attrDone) {
        cudaFuncSetAttribute(gemm_h<128>, cudaFuncAttributeMaxDynamicSharedMemorySize, SM128);
        cudaFuncSetAttribute(gemm_h<64>,  cudaFuncAttributeMaxDynamicSharedMemorySize, SM64);
        attrDone = 1;
    }

    void* tp;
#define GETSYMF(var, sym) cudaGetSymbolAddress(&tp, sym); float* var = (float*)tp
#define GETSYMH(var, sym) cudaGetSymbolAddress(&tp, sym); __half* var = (__half*)tp
    GETSYMH(ph_gcatT, h_gcatT); GETSYMH(ph_wqkvT, h_wqkvT); GETSYMH(ph_w2qkT, h_w2qkT);
    GETSYMH(ph_WoT, h_WoT);     GETSYMH(ph_W1T, h_W1T);     GETSYMH(ph_W2T, h_W2T);
    GETSYMH(ph_sig, h_sig);     GETSYMH(ph_ln1, h_ln1);     GETSYMH(ph_a1, h_a1);
    GETSYMH(ph_mug, h_mug);     GETSYMH(ph_attn, h_attn);   GETSYMH(ph_o, h_o);
    GETSYMH(ph_ln2, h_ln2);     GETSYMH(ph_hh, h_hh);       GETSYMH(ph_hid, h_hid);
    GETSYMH(ph_beta, h_beta);   GETSYMH(ph_bm, h_bm);       GETSYMH(ph_vT, h_vT);
    GETSYMH(ph_ln2T, h_ln2T);   GETSYMH(ph_hT, h_hT);       GETSYMH(ph_Z, h_Z);
    GETSYMF(pg_ln1, g_ln1);     GETSYMF(pg_qkv, g_qkv);     GETSYMF(pg_s2, g_s2);
    GETSYMF(pg_o, g_o);         GETSYMF(pg_res, g_res);     GETSYMF(pg_ln2, g_ln2);
    GETSYMF(pg_h, g_h);         GETSYMF(pg_bh, g_bh);
#undef GETSYMF
#undef GETSYMH

    const int EW = 256;
    const int GB_BNK = BNK_ / EW;
    dim3 tb(32, 8);

    // ---- prep ----
    copy_h_kernel<<<(KG_ * K_ + EW - 1) / EW, EW>>>(gen, ph_gcatT, KG_ * K_);
    copy_h_kernel<<<(BNK_ + EW - 1) / EW, EW>>>(sigma_q, ph_sig, BNK_);
    wtr_h_kernel<<<dim3(16, 16), tb>>>(Wq, ph_wqkvT, K_, K_, 0);
    wtr_h_kernel<<<dim3(16, 16), tb>>>(Wk, ph_wqkvT + K_ * K_, K_, K_, 0);
    wtr_h_kernel<<<dim3(16, 16), tb>>>(Wv, ph_wqkvT + 2 * K_ * K_, K_, K_, 0);
    wtr_h_kernel<<<dim3(16, 16), tb>>>(Wq, ph_w2qkT, K_, K_, 1);
    wtr_h_kernel<<<dim3(16, 16), tb>>>(Wk, ph_w2qkT + K_ * K_, K_, K_, 1);
    wtr_h_kernel<<<dim3(16, 16), tb>>>(Wo, ph_WoT, K_, K_, 0);
    wtr_h_kernel<<<dim3(64, 16), tb>>>(W1, ph_W1T, K_, HID_, 0);
    wtr_h_kernel<<<dim3(16, 64), tb>>>(W2, ph_W2T, HID_, K_, 0);

    // ---- attention sublayer ----
    ln_kernel<<<BN_, 256>>>(mu_q, g1, be1, pg_ln1, ph_ln1);
    launch_gh(ph_ln1, ph_gcatT, nullptr, ph_Z, BN_, KG_, K_, K_, KG_,
              0,0,0,0,0,0, 1, 1, 0, 4);
    combine1_kernel<<<GB_BNK, EW>>>(phi, 1.f);
    launch_gh(ph_a1, ph_gcatT, nullptr, ph_Z, BN_, KG_, K_, K_, KG_,
              0,0,0,0,0,0, 1, 1, 0, 4);
    combine2_kernel<<<GB_BNK, EW>>>(phi, 1.f, pg_ln1, nullptr, nullptr, ph_mug);

    launch_gh(ph_mug, ph_wqkvT, pg_qkv, nullptr, BN_, QKVW_, K_, K_, QKVW_,
              0,0,0,0,0,0, 1, 1, 0, 0);
    launch_gh(ph_sig, ph_w2qkT, pg_s2, nullptr, BN_, 2 * K_, K_, K_, 2 * K_,
              0,0,0,0,0,0, 1, 1, 0, 0);

    prep_attn_gamdel_kernel<<<BN_, 256>>>();
    tr2h_kernel<<<dim3(16, 32, B_), tb>>>(pg_qkv + 2 * K_, ph_vT, QKVW_,
                                          (long long)N_ * QKVW_, (long long)K_ * N_);
    score_kernel<<<dim3(N_ / 64, N_ / 64, B_ * H_), 256>>>();
    softmax_bm_kernel<<<BN_, 256>>>();

    launch_gh(ph_beta, ph_vT, nullptr, ph_attn, N_, DH_, N_, N_, K_,
              8LL * NN_, (long long)NN_,
              (long long)K_ * N_, 64LL * N_,
              (long long)N_ * K_, 64, H_, B_ * H_, 1, 4);

    launch_gh(ph_attn, ph_WoT, pg_o, ph_o, BN_, K_, K_, K_, K_,
              0,0,0,0,0,0, 1, 1, 0, 5);
    launch_gh(ph_o, ph_gcatT, nullptr, ph_Z, BN_, KG_, K_, K_, KG_,
              0,0,0,0,0,0, 1, 1, 0, 4);
    combine1_kernel<<<GB_BNK, EW>>>(phi, -1.f);
    launch_gh(ph_a1, ph_gcatT, nullptr, ph_Z, BN_, KG_, K_, K_, KG_,
              0,0,0,0,0,0, 1, 1, 0, 4);
    combine2_kernel<<<GB_BNK, EW>>>(phi, -1.f, pg_o, mu_q, pg_res, nullptr);

    // ---- FFN sublayer ----
    ln_kernel<<<BN_, 256>>>(pg_res, g2, be2, pg_ln2, ph_ln2);
    tr2h_kernel<<<dim3(16, 32, B_), tb>>>(pg_ln2, ph_ln2T, K_,
                                          (long long)N_ * K_, (long long)K_ * N_);
    float* out = (float*)d_out;

    launch_gh(ph_bm, ph_ln2T, pg_bh, nullptr, N_, K_, N_, N_, K_,
              (long long)NN_, 0, (long long)K_ * N_, 0, (long long)N_ * K_, 0,
              1, B_, 1, 0);
    launch_gh(ph_ln2, ph_W1T, nullptr, ph_hid, BN_, HID_, K_, K_, HID_,
              0,0,0,0,0,0, 1, 1, 0, 1, bh1);
    launch_gh(ph_hid, ph_W2T, pg_h, ph_hh, BN_, K_, HID_, HID_, K_,
              0,0,0,0,0,0, 1, 1, 0, 2, bh2, pg_ln2, mu_prior, pg_bh, lr);

    tr2h_kernel<<<dim3(16, 32, B_), tb>>>(pg_h, ph_hT, K_,
                                          (long long)N_ * K_, (long long)K_ * N_);
    launch_gh(ph_bm, ph_hT, pg_bh, nullptr, N_, K_, N_, N_, K_,
              (long long)NN_, 0, (long long)K_ * N_, 0, (long long)N_ * K_, 0,
              1, B_, 1, 0);
    launch_gh(ph_hh, ph_W1T, nullptr, ph_hid, BN_, HID_, K_, K_, HID_,
              0,0,0,0,0,0, 1, 1, 0, 1, bh1);
    launch_gh(ph_hid, ph_W2T, out, nullptr, BN_, K_, HID_, HID_, K_,
              0,0,0,0,0,0, 1, 1, 0, 3, bh2, pg_h, mu_prior, pg_bh, lr, pg_res, pg_ln2);

    cudaMemcpyAsync(out + BNK_, sigma_q, (size_t)BNK_ * sizeof(float),
                    cudaMemcpyDeviceToDevice);
    cudaMemcpyAsync(out + 2 * (size_t)BNK_, phi, (size_t)B_ * N_ * 3 * sizeof(float),
                    cudaMemcpyDeviceToDevice);
}

// round 10
// speedup vs baseline: 1.8345x; 1.0475x over previous
#include <cuda_runtime.h>
#include <cuda_fp16.h>
#include <math.h>
#include <stdint.h>

#define B_   4
#define N_   1024
#define K_   512
#define H_   8
#define DH_  64
#define HID_ 2048
#define KG_  (3*K_)
#define BN_  (B_*N_)
#define BNK_ (B_*N_*K_)
#define BHN_ (B_*H_*N_)
#define NN_  (N_*N_)
#define QKVW_ (3*K_)

// ---------------- device scratch ----------------
__device__ __half h_gcatT[KG_*K_];
__device__ __half h_wqkvT[QKVW_*K_];
__device__ __half h_w2qkT[2*K_*K_];
__device__ __half h_WoT[K_*K_];
__device__ __half h_W1T[HID_*K_];
__device__ __half h_W2T[K_*HID_];
__device__ __half h_sig[BNK_];
__device__ __half h_ln1[BNK_];
__device__ __half h_a1[BNK_];
__device__ __half h_mug[BNK_];
__device__ __half h_attn[BNK_];
__device__ __half h_ln2[BNK_];
__device__ __half h_hh[BNK_];
__device__ __half h_hid[BN_*HID_];
__device__ __half h_beta[33554432];
__device__ __half h_bm[B_*NN_];
__device__ __half h_vT[BNK_];
__device__ __half h_ln2T[BNK_];
__device__ __half h_hT[BNK_];
__device__ __half h_Z[BN_*KG_];
__device__ __half h_Qe[BHN_*2*DH_];
__device__ __half h_Ke[BHN_*2*DH_];
__device__ __half h_o[BNK_];
__device__ float g_ln1[BNK_];
__device__ float g_qkv[BN_*QKVW_];
__device__ float g_s2[BN_*2*K_];
__device__ float g_gam[BHN_];
__device__ float g_del[BHN_];
__device__ float g_beta[33554432];
__device__ float g_o[BNK_];
__device__ float g_res[BNK_];
__device__ float g_ln2[BNK_];
__device__ float g_h[BNK_];
__device__ float g_bh[BNK_];

// ---------------- helpers ----------------
__device__ __forceinline__ float warpSum(float v) {
#pragma unroll
    for (int o = 16; o; o >>= 1) v += __shfl_down_sync(0xffffffffu, v, o);
    return v;
}
__device__ __forceinline__ float allMax(float v) {
#pragma unroll
    for (int o = 16; o; o >>= 1) v = fmaxf(v, __shfl_xor_sync(0xffffffffu, v, o));
    return v;
}
__device__ __forceinline__ float allSum(float v) {
#pragma unroll
    for (int o = 16; o; o >>= 1) v += __shfl_xor_sync(0xffffffffu, v, o);
    return v;
}
__device__ __forceinline__ void cpa16(void* s, const void* g) {
    unsigned sa = (unsigned)__cvta_generic_to_shared(s);
    asm volatile("cp.async.cg.shared.global [%0], [%1], 16;" :: "r"(sa), "l"(g));
}
__device__ __forceinline__ float gelu_f(float x) {
    float x3 = x * x * x;
    return 0.5f * x * (1.f + tanhf(0.7978845608028654f * (x + 0.044715f * x3)));
}
#define LDSM4(R, addr) \
    asm volatile("ldmatrix.sync.aligned.m8n8.x4.shared.b16 {%0,%1,%2,%3}, [%4];" \
                 : "=r"((R)[0]), "=r"((R)[1]), "=r"((R)[2]), "=r"((R)[3]) : "r"(addr))
#define MMA16816(D, A, B0, B1) \
    asm volatile("mma.sync.aligned.m16n8k16.row.col.f32.f16.f16.f32 " \
                 "{%0,%1,%2,%3}, {%4,%5,%6,%7}, {%8,%9}, {%0,%1,%2,%3};" \
                 : "+f"((D)[0]), "+f"((D)[1]), "+f"((D)[2]), "+f"((D)[3]) \
                 : "r"((A)[0]), "r"((A)[1]), "r"((A)[2]), "r"((A)[3]), "r"(B0), "r"(B1))

// ============ fp16 tensor-core GEMM: C = A[M,Kd](fp16) @ Bt^T, Bt = [N][Kd] fp16 ============
// epi: 0 fp32; 1 gelu->fp16; 2 VFE->fp32+fp16; 3 VFE+final->fp32; 4 fp16; 5 fp32+fp16
template<int BN>
__global__ __launch_bounds__(256, 2)
void gemm_h(const __half* __restrict__ A, const __half* __restrict__ Bt,
            float* __restrict__ C, __half* __restrict__ C16,
            int Kd, int lda, int ldc,
            long long sAo, long long sAi, long long sBo, long long sBi,
            long long sCo, long long sCi, int innerDiv, int causal, int epi,
            const float* __restrict__ bias,
            const float* __restrict__ e_hin,  const float* __restrict__ e_prior,
            const float* __restrict__ e_aux,  const float* __restrict__ e_lr,
            const float* __restrict__ e_res,  const float* __restrict__ e_ln2)
{
    constexpr int BM = 128, LD = 40;
    constexpr int WN = BN / 2;
    constexpr int NF = BN / 16;
    extern __shared__ __half hsm[];
    __half* sA = hsm;
    __half* sB = hsm + 3 * BM * LD;

    int z = blockIdx.z;
    int zo = z / innerDiv, zi = z - zo * innerDiv;
    A  += zo * sAo + zi * sAi;
    Bt += zo * sBo + zi * sBi;
    long long coff = zo * sCo + zi * sCi;

    int tid = threadIdx.x;
    int wid = tid >> 5, lane = tid & 31;
    int wm = wid & 3, wn = wid >> 2;
    int row0 = blockIdx.y * BM, col0 = blockIdx.x * BN;
    int gid = lane >> 2, tig = lane & 3;
    int l8 = lane & 7, lm = lane >> 3;
    int aRow = (lm & 1) * 8 + l8, aCol = (lm >> 1) * 8;
    int bRow = (lm >> 1) * 8 + l8, bCol = (lm & 1) * 8;

    float acc[2][NF][4];
#pragma unroll
    for (int mi = 0; mi < 2; mi++)
#pragma unroll
        for (int ni = 0; ni < NF; ni++)
#pragma unroll
            for (int r = 0; r < 4; r++) acc[mi][ni][r] = 0.f;

    int kTiles = Kd / 32;
    if (causal) { int lim = (row0 + BM) / 32; if (lim < kTiles) kTiles = lim; }

    auto loadTile = [&](int t) {
        int buf = t % 3;
        int k0 = t * 32;
        __half* pA = sA + buf * BM * LD;
        __half* pB = sB + buf * BN * LD;
#pragma unroll
        for (int i = tid; i < BM * 4; i += 256) {
            int m = i >> 2, u = i & 3;
            cpa16(&pA[m * LD + u * 8], A + (size_t)(row0 + m) * lda + k0 + u * 8);
        }
#pragma unroll
        for (int i = tid; i < BN * 4; i += 256) {
            int n = i >> 2, u = i & 3;
            cpa16(&pB[n * LD + u * 8], Bt + (size_t)(col0 + n) * Kd + k0 + u * 8);
        }
        asm volatile("cp.async.commit_group;");
    };

    loadTile(0);
    if (kTiles > 1) loadTile(1);
    else asm volatile("cp.async.commit_group;");

    for (int t = 0; t < kTiles; t++) {
        asm volatile("cp.async.wait_group 1;");
        __syncthreads();
        if (t + 2 < kTiles) loadTile(t + 2);
        else asm volatile("cp.async.commit_group;");
        int buf = t % 3;
        const __half* pA = sA + buf * BM * LD;
        const __half* pB = sB + buf * BN * LD;
#pragma unroll
        for (int ks = 0; ks < 2; ks++) {
            int kb0 = ks * 16;
            uint32_t a[2][4];
#pragma unroll
            for (int mi = 0; mi < 2; mi++) {
                unsigned ad = (unsigned)__cvta_generic_to_shared(
                    &pA[(wm * 32 + mi * 16 + aRow) * LD + kb0 + aCol]);
                LDSM4(a[mi], ad);
            }
#pragma unroll
            for (int ni2 = 0; ni2 < NF / 2; ni2++) {
                uint32_t bb[4];
                unsigned bd = (unsigned)__cvta_generic_to_shared(
                    &pB[(wn * WN + ni2 * 16 + bRow) * LD + kb0 + bCol]);
                LDSM4(bb, bd);
#pragma unroll
                for (int mi = 0; mi < 2; mi++) {
                    MMA16816(acc[mi][2 * ni2],     a[mi], bb[0], bb[1]);
                    MMA16816(acc[mi][2 * ni2 + 1], a[mi], bb[2], bb[3]);
                }
            }
        }
        __syncthreads();
    }

    float lrv = (epi == 2 || epi == 3) ? e_lr[0] : 0.f;
    bool w32 = (epi == 0 || epi == 2 || epi == 3 || epi == 5);
    bool w16 = (epi == 1 || epi == 2 || epi == 4 || epi == 5);
#pragma unroll
    for (int mi = 0; mi < 2; mi++) {
#pragma unroll
        for (int ni = 0; ni < NF; ni++) {
            int cb = col0 + wn * WN + ni * 8 + 2 * tig;
#pragma unroll
            for (int hf = 0; hf < 2; hf++) {
                int rr = row0 + wm * 32 + mi * 16 + gid + hf * 8;
                float v0 = acc[mi][ni][hf * 2], v1 = acc[mi][ni][hf * 2 + 1];
                long long off = coff + (long long)rr * ldc + cb;
                if (epi == 1) {
                    v0 = gelu_f(v0 + bias[cb]);
                    v1 = gelu_f(v1 + bias[cb + 1]);
                } else if (epi == 2 || epi == 3) {
                    float x0 = v0 + bias[cb], x1 = v1 + bias[cb + 1];
                    float h0 = e_hin[off], h1 = e_hin[off + 1];
                    v0 = h0 + lrv * (x0 - (1e-3f * (h0 - e_prior[off]) + (h0 - e_aux[off])));
                    v1 = h1 + lrv * (x1 - (1e-3f * (h1 - e_prior[off + 1]) + (h1 - e_aux[off + 1])));
                    if (epi == 3) {
                        v0 = e_res[off] + v0 - e_ln2[off];
                        v1 = e_res[off + 1] + v1 - e_ln2[off + 1];
                    }
                }
                if (w32) { float2 f2; f2.x = v0; f2.y = v1; *(float2*)&C[off] = f2; }
                if (w16) { *(__half2*)&C16[off] = __floats2half2_rn(v0, v1); }
            }
        }
    }
}

// ---------------- prep kernels ----------------
__global__ void wtr_h_kernel(const float* __restrict__ src, __half* __restrict__ dst,
                             int R, int C, int sq)
{
    __shared__ float t[32][33];
    int bx = blockIdx.x * 32, by = blockIdx.y * 32;
    int x = bx + threadIdx.x;
#pragma unroll
    for (int i = 0; i < 32; i += 8) {
        int y = by + threadIdx.y + i;
        float v = src[(size_t)y * C + x];
        if (sq) v = v * v;
        t[threadIdx.y + i][threadIdx.x] = v;
    }
    __syncthreads();
    int xo = by + threadIdx.x;
#pragma unroll
    for (int i = 0; i < 32; i += 8) {
        int yo = bx + threadIdx.y + i;
        dst[(size_t)yo * R + xo] = __float2half_rn(t[threadIdx.x][threadIdx.y + i]);
    }
}
__global__ void copy_h_kernel(const float* __restrict__ src, __half* __restrict__ dst, int n)
{
    int i = blockIdx.x * 256 + threadIdx.x;
    if (i < n) dst[i] = __float2half_rn(src[i]);
}
__global__ void tr2h_kernel(const float* __restrict__ src, __half* __restrict__ dst,
                            int srcRow, long long sSrcB, long long sDstB)
{
    __shared__ float t[32][33];
    const float* s = src + blockIdx.z * sSrcB;
    __half* d = dst + blockIdx.z * sDstB;
    int f0 = blockIdx.x * 32, t0 = blockIdx.y * 32;
#pragma unroll
    for (int i = 0; i < 32; i += 8)
        t[threadIdx.y + i][threadIdx.x] =
            s[(size_t)(t0 + threadIdx.y + i) * srcRow + f0 + threadIdx.x];
    __syncthreads();
#pragma unroll
    for (int i = 0; i < 32; i += 8)
        d[(size_t)(f0 + threadIdx.y + i) * 1024 + t0 + threadIdx.x] =
            __float2half_rn(t[threadIdx.x][threadIdx.y + i]);
}

// ---------------- layernorm (fp32 out + fp16 twin) ----------------
__global__ void ln_kernel(const float* __restrict__ x, const float* __restrict__ gw,
                          const float* __restrict__ bw, float* __restrict__ y,
                          __half* __restrict__ yh)
{
    int bn = blockIdx.x;
    const float* xr = x + (long long)bn * K_;
    int t = threadIdx.x;
    float v0 = xr[t], v1 = xr[t + 256];
    __shared__ float red[8];
    __shared__ float s_mean, s_rstd;
    int lane = t & 31, w = t >> 5;
    float s = warpSum(v0 + v1);
    if (lane == 0) red[w] = s;
    __syncthreads();
    if (t == 0) {
        float tot = 0.f;
        for (int i = 0; i < 8; i++) tot += red[i];
        s_mean = tot * (1.f / 512.f);
    }
    __syncthreads();
    float m = s_mean;
    float d0 = v0 - m, d1 = v1 - m;
    float s2 = warpSum(d0 * d0 + d1 * d1);
    if (lane == 0) red[w] = s2;
    __syncthreads();
    if (t == 0) {
        float tot = 0.f;
        for (int i = 0; i < 8; i++) tot += red[i];
        s_rstd = rsqrtf(tot * (1.f / 512.f) + 1e-5f);
    }
    __syncthreads();
    float r = s_rstd;
    float o0 = d0 * r * gw[t] + bw[t];
    float o1 = d1 * r * gw[t + 256] + bw[t + 256];
    long long base = (long long)bn * K_;
    if (y) { y[base + t] = o0; y[base + t + 256] = o1; }
    if (yh) {
        yh[base + t] = __float2half_rn(o0);
        yh[base + t + 256] = __float2half_rn(o1);
    }
}

// ---------------- transport combines (fp16 Z) ----------------
__global__ void combine1_kernel(const float* __restrict__ phi, float sign)
{
    int i = blockIdx.x * 256 + threadIdx.x;
    if (i >= BNK_) return;
    int bn = i >> 9, k = i & (K_ - 1);
    const float* pp = phi + bn * 3;
    const __half* z = h_Z + (long long)bn * KG_;
    float v = sign * (pp[0] * __half2float(z[k]) + pp[1] * __half2float(z[K_ + k])
                    + pp[2] * __half2float(z[2 * K_ + k]));
    h_a1[i] = __float2half_rn(v);
}
__global__ void combine2_kernel(const float* __restrict__ phi, float sign,
                                const float* __restrict__ xbase,
                                const float* __restrict__ resid,
                                float* __restrict__ out32, __half* __restrict__ out16)
{
    int i = blockIdx.x * 256 + threadIdx.x;
    if (i >= BNK_) return;
    int bn = i >> 9, k = i & (K_ - 1);
    const float* pp = phi + bn * 3;
    const __half* z = h_Z + (long long)bn * KG_;
    float c = sign * (pp[0] * __half2float(z[k]) + pp[1] * __half2float(z[K_ + k])
                    + pp[2] * __half2float(z[2 * K_ + k]));
    float r = xbase[i] + __half2float(h_a1[i]) + 0.5f * c;
    if (resid) r += resid[i];
    if (out32) out32[i] = r;
    if (out16) out16[i] = __float2half_rn(r);
}

// ---------------- fused attention prep -> fp16 Qe/Ke + gamma/delta ----------------
__global__ void prep_attn_gamdel_kernel()
{
    int bn = blockIdx.x;
    int b = bn >> 10, n = bn & (N_ - 1);
    int t = threadIdx.x;
    int lane = t & 31;
    __shared__ float sacc[3][H_];
    if (t < 3 * H_) ((float*)sacc)[t] = 0.f;
    __syncthreads();
#pragma unroll
    for (int half = 0; half < 2; half++) {
        int k = t + half * 256;
        long long s2b = (long long)bn * (2 * K_);
        long long qb  = (long long)bn * QKVW_;
        float sqraw = g_s2[s2b + k] + 1e-8f;
        float inv = 1.f / sqraw;
        float q = g_qkv[qb + k];
        float sk = g_s2[s2b + K_ + k] + 1e-8f;
        float kv = g_qkv[qb + K_ + k];
        int h = k >> 6, d = k & 63;
        size_t qe = (((size_t)(b * H_ + h)) * N_ + n) * 128 + d;
        h_Qe[qe]      = __float2half_rn(-0.5f * inv);
        h_Qe[qe + 64] = __float2half_rn(q * inv);
        h_Ke[qe]      = __float2half_rn(sk + kv * kv);
        h_Ke[qe + 64] = __float2half_rn(kv);
        float qq  = q * q * inv;
        float lsq = logf(sqraw);
        float lsk = logf(sk);
        qq = warpSum(qq); lsq = warpSum(lsq); lsk = warpSum(lsk);
        if (lane == 0) {
            atomicAdd(&sacc[0][h], qq);
            atomicAdd(&sacc[1][h], lsq);
            atomicAdd(&sacc[2][h], lsk);
        }
    }
    __syncthreads();
    if (t < H_) {
        int idx = ((b * H_ + t) * N_) + n;
        g_gam[idx] = -0.5f * (sacc[0][t] - (float)DH_ + sacc[1][t]);
        g_del[idx] = 0.5f * sacc[2][t];
    }
}

// ---------------- KL score: fp16 mma + ldmatrix, 64x64 tiles, K=128 ----------------
__global__ __launch_bounds__(256) void score_kernel()
{
    int bh = blockIdx.z;
    int i0 = blockIdx.y * 64, j0 = blockIdx.x * 64;
    if (j0 > i0) return;
    constexpr int LD = 136;
    __shared__ __half Qs[64 * LD];
    __shared__ __half Ks[64 * LD];
    int tid = threadIdx.x;
    int wid = tid >> 5, lane = tid & 31;
    int wm = wid & 3, wn = wid >> 2;
    int gid = lane >> 2, tig = lane & 3;
    int l8 = lane & 7, lm = lane >> 3;
    int aRow = (lm & 1) * 8 + l8, aCol = (lm >> 1) * 8;
    int bRow = (lm >> 1) * 8 + l8, bCol = (lm & 1) * 8;

    const __half* Qsrc = h_Qe + (((size_t)bh) * N_ + i0) * 128;
    const __half* Ksrc = h_Ke + (((size_t)bh) * N_ + j0) * 128;
    for (int i = tid; i < 1024; i += 256) {
        int r = i >> 4, u = (i & 15) * 8;
        cpa16(&Qs[r * LD + u], Qsrc + (size_t)r * 128 + u);
        cpa16(&Ks[r * LD + u], Ksrc + (size_t)r * 128 + u);
    }
    asm volatile("cp.async.commit_group;");
    asm volatile("cp.async.wait_group 0;");
    __syncthreads();

    float acc[4][4] = {};
#pragma unroll
    for (int ks = 0; ks < 8; ks++) {
        int kb0 = ks * 16;
        uint32_t a[4];
        unsigned ad = (unsigned)__cvta_generic_to_shared(
            &Qs[(wm * 16 + aRow) * LD + kb0 + aCol]);
        LDSM4(a, ad);
#pragma unroll
        for (int ni2 = 0; ni2 < 2; ni2++) {
            uint32_t bb[4];
            unsigned bd = (unsigned)__cvta_generic_to_shared(
                &Ks[(wn * 32 + ni2 * 16 + bRow) * LD + kb0 + bCol]);
            LDSM4(bb, bd);
            MMA16816(acc[2 * ni2],     a, bb[0], bb[1]);
            MMA16816(acc[2 * ni2 + 1], a, bb[2], bb[3]);
        }
    }

    long long gdb = (long long)bh * N_;
#pragma unroll
    for (int hf = 0; hf < 2; hf++) {
        int i = i0 + wm * 16 + gid + hf * 8;
        float gv = g_gam[gdb + i];
#pragma unroll
        for (int ni = 0; ni < 4; ni++) {
            int j = j0 + wn * 32 + ni * 8 + 2 * tig;
            float2 o;
            o.x = acc[ni][hf * 2 + 0] + gv + g_del[gdb + j];
            o.y = acc[ni][hf * 2 + 1] + gv + g_del[gdb + j + 1];
            *(float2*)&g_beta[(gdb + i) * N_ + j] = o;
        }
    }
}

// ---------------- softmax: 1 warp per (head,row) + fused beta_m ----------------
__global__ __launch_bounds__(256) void softmax_bm_kernel()
{
    int bi = blockIdx.x;
    int b = bi >> 10, i = bi & (N_ - 1);
    int Jmax = ((i >> 7) + 1) << 7;
    int tid = threadIdx.x;
    int w = tid >> 5, lane = tid & 31;
    __shared__ float bmbuf[H_][N_];

    long long rowoff = (((long long)(b * H_ + w)) * N_ + i) * N_;
    const float* p = g_beta + rowoff;
    __half* ph = h_beta + rowoff;

    float ev[32];
    float m = -1e30f;
#pragma unroll
    for (int jj = 0; jj < 32; jj++) {
        int j = lane + jj * 32;
        float v = (j <= i) ? p[j] : -1e30f;
        ev[jj] = v;
        m = fmaxf(m, v);
    }
    m = allMax(m);
    float s = 0.f;
#pragma unroll
    for (int jj = 0; jj < 32; jj++) {
        ev[jj] = (lane + jj * 32 <= i) ? expf(ev[jj] - m) : 0.f;
        s += ev[jj];
    }
    s = allSum(s);
    float inv = 1.f / s;
#pragma unroll
    for (int jj = 0; jj < 32; jj++) {
        int j = lane + jj * 32;
        if (j < Jmax) {
            float v = ev[jj] * inv;
            ph[j] = __float2half_rn(v);
            bmbuf[w][j] = v;
        }
    }
    __syncthreads();
    __half* bm = h_bm + ((long long)b * N_ + i) * N_;
    for (int j = tid; j < Jmax; j += 256) {
        float t = 0.f;
#pragma unroll
        for (int h = 0; h < H_; h++) t += bmbuf[h][j];
        bm[j] = __float2half_rn(t * 0.125f);
    }
}

// ---------------- host ----------------
#define SM128 (3 * (128 * 40 + 128 * 40) * 2)   // 61440
#define SM64  (3 * (128 * 40 + 64 * 40) * 2)    // 46080
static inline void launch_gh(const __half* A, const __half* Bt, float* C, __half* C16,
                             int M, int Ncols, int Kd, int lda, int ldc,
                             long long sAo, long long sAi, long long sBo, long long sBi,
                             long long sCo, long long sCi, int innerDiv, int batch,
                             int causal, int epi,
                             const float* bias = nullptr,
                             const float* e_hin = nullptr, const float* e_prior = nullptr,
                             const float* e_aux = nullptr, const float* e_lr = nullptr,
                             const float* e_res = nullptr, const float* e_ln2 = nullptr)
{
    if (Ncols % 128 == 0) {
        dim3 g(Ncols / 128, M / 128, batch);
        gemm_h<128><<<g, 256, SM128>>>(A, Bt, C, C16, Kd, lda, ldc,
                                       sAo, sAi, sBo, sBi, sCo, sCi, innerDiv, causal, epi,
                                       bias, e_hin, e_prior, e_aux, e_lr, e_res, e_ln2);
    } else {
        dim3 g(Ncols / 64, M / 128, batch);
        gemm_h<64><<<g, 256, SM64>>>(A, Bt, C, C16, Kd, lda, ldc,
                                     sAo, sAi, sBo, sBi, sCo, sCi, innerDiv, causal, epi,
                                     bias, e_hin, e_prior, e_aux, e_lr, e_res, e_ln2);
    }
}

extern "C" void kernel_launch(void* const* d_in, const int* in_sizes, int n_in,
                              void* d_out, int out_size)
{
    const float* mu_q     = (const float*)d_in[0];
    const float* sigma_q  = (const float*)d_in[1];
    const float* phi      = (const float*)d_in[2];
    const float* gen      = (const float*)d_in[3];
    const float* mu_prior = (const float*)d_in[5];
    const float* Wq  = (const float*)d_in[6];
    const float* Wk  = (const float*)d_in[7];
    const float* Wv  = (const float*)d_in[8];
    const float* Wo  = (const float*)d_in[9];
    const float* g1  = (const float*)d_in[10];
    const float* be1 = (const float*)d_in[11];
    const float* g2  = (const float*)d_in[12];
    const float* be2 = (const float*)d_in[13];
    const float* W1  = (const float*)d_in[14];
    const float* bh1 = (const float*)d_in[15];
    const float* W2  = (const float*)d_in[16];
    const float* bh2 = (const float*)d_in[17];
    const float* lr  = (const float*)d_in[18];

    static int attrDone = 0;
    if (!attrDone) {
        cudaFuncSetAttribute(gemm_h<128>, cudaFuncAttributeMaxDynamicSharedMemorySize, SM128);
        cudaFuncSetAttribute(gemm_h<64>,  cudaFuncAttributeMaxDynamicSharedMemorySize, SM64);
        attrDone = 1;
    }

    void* tp;
#define GETSYMF(var, sym) cudaGetSymbolAddress(&tp, sym); float* var = (float*)tp
#define GETSYMH(var, sym) cudaGetSymbolAddress(&tp, sym); __half* var = (__half*)tp
    GETSYMH(ph_gcatT, h_gcatT); GETSYMH(ph_wqkvT, h_wqkvT); GETSYMH(ph_w2qkT, h_w2qkT);
    GETSYMH(ph_WoT, h_WoT);     GETSYMH(ph_W1T, h_W1T);     GETSYMH(ph_W2T, h_W2T);
    GETSYMH(ph_sig, h_sig);     GETSYMH(ph_ln1, h_ln1);     GETSYMH(ph_a1, h_a1);
    GETSYMH(ph_mug, h_mug);     GETSYMH(ph_attn, h_attn);   GETSYMH(ph_o, h_o);
    GETSYMH(ph_ln2, h_ln2);     GETSYMH(ph_hh, h_hh);       GETSYMH(ph_hid, h_hid);
    GETSYMH(ph_beta, h_beta);   GETSYMH(ph_bm, h_bm);       GETSYMH(ph_vT, h_vT);
    GETSYMH(ph_ln2T, h_ln2T);   GETSYMH(ph_hT, h_hT);       GETSYMH(ph_Z, h_Z);
    GETSYMF(pg_ln1, g_ln1);     GETSYMF(pg_qkv, g_qkv);     GETSYMF(pg_s2, g_s2);
    GETSYMF(pg_o, g_o);         GETSYMF(pg_res, g_res);     GETSYMF(pg_ln2, g_ln2);
    GETSYMF(pg_h, g_h);         GETSYMF(pg_bh, g_bh);
#undef GETSYMF
#undef GETSYMH

    const int EW = 256;
    const int GB_BNK = BNK_ / EW;
    dim3 tb(32, 8);

    // ---- prep ----
    copy_h_kernel<<<(KG_ * K_ + EW - 1) / EW, EW>>>(gen, ph_gcatT, KG_ * K_);
    copy_h_kernel<<<(BNK_ + EW - 1) / EW, EW>>>(sigma_q, ph_sig, BNK_);
    wtr_h_kernel<<<dim3(16, 16), tb>>>(Wq, ph_wqkvT, K_, K_, 0);
    wtr_h_kernel<<<dim3(16, 16), tb>>>(Wk, ph_wqkvT + K_ * K_, K_, K_, 0);
    wtr_h_kernel<<<dim3(16, 16), tb>>>(Wv, ph_wqkvT + 2 * K_ * K_, K_, K_, 0);
    wtr_h_kernel<<<dim3(16, 16), tb>>>(Wq, ph_w2qkT, K_, K_, 1);
    wtr_h_kernel<<<dim3(16, 16), tb>>>(Wk, ph_w2qkT + K_ * K_, K_, K_, 1);
    wtr_h_kernel<<<dim3(16, 16), tb>>>(Wo, ph_WoT, K_, K_, 0);
    wtr_h_kernel<<<dim3(64, 16), tb>>>(W1, ph_W1T, K_, HID_, 0);
    wtr_h_kernel<<<dim3(16, 64), tb>>>(W2, ph_W2T, HID_, K_, 0);

    // ---- attention sublayer ----
    ln_kernel<<<BN_, 256>>>(mu_q, g1, be1, pg_ln1, ph_ln1);
    launch_gh(ph_ln1, ph_gcatT, nullptr, ph_Z, BN_, KG_, K_, K_, KG_,
              0,0,0,0,0,0, 1, 1, 0, 4);
    combine1_kernel<<<GB_BNK, EW>>>(phi, 1.f);
    launch_gh(ph_a1, ph_gcatT, nullptr, ph_Z, BN_, KG_, K_, K_, KG_,
              0,0,0,0,0,0, 1, 1, 0, 4);
    combine2_kernel<<<GB_BNK, EW>>>(phi, 1.f, pg_ln1, nullptr, nullptr, ph_mug);

    launch_gh(ph_mug, ph_wqkvT, pg_qkv, nullptr, BN_, QKVW_, K_, K_, QKVW_,
              0,0,0,0,0,0, 1, 1, 0, 0);
    launch_gh(ph_sig, ph_w2qkT, pg_s2, nullptr, BN_, 2 * K_, K_, K_, 2 * K_,
              0,0,0,0,0,0, 1, 1, 0, 0);

    prep_attn_gamdel_kernel<<<BN_, 256>>>();
    tr2h_kernel<<<dim3(16, 32, B_), tb>>>(pg_qkv + 2 * K_, ph_vT, QKVW_,
                                          (long long)N_ * QKVW_, (long long)K_ * N_);
    score_kernel<<<dim3(N_ / 64, N_ / 64, B_ * H_), 256>>>();
    softmax_bm_kernel<<<BN_, 256>>>();

    launch_gh(ph_beta, ph_vT, nullptr, ph_attn, N_, DH_, N_, N_, K_,
              8LL * NN_, (long long)NN_,
              (long long)K_ * N_, 64LL * N_,
              (long long)N_ * K_, 64, H_, B_ * H_, 1, 4);

    launch_gh(ph_attn, ph_WoT, pg_o, ph_o, BN_, K_, K_, K_, K_,
              0,0,0,0,0,0, 1, 1, 0, 5);
    launch_gh(ph_o, ph_gcatT, nullptr, ph_Z, BN_, KG_, K_, K_, KG_,
              0,0,0,0,0,0, 1, 1, 0, 4);
    combine1_kernel<<<GB_BNK, EW>>>(phi, -1.f);
    launch_gh(ph_a1, ph_gcatT, nullptr, ph_Z, BN_, KG_, K_, K_, KG_,
              0,0,0,0,0,0, 1, 1, 0, 4);
    combine2_kernel<<<GB_BNK, EW>>>(phi, -1.f, pg_o, mu_q, pg_res, nullptr);

    // ---- FFN sublayer ----
    ln_kernel<<<BN_, 256>>>(pg_res, g2, be2, pg_ln2, ph_ln2);
    tr2h_kernel<<<dim3(16, 32, B_), tb>>>(pg_ln2, ph_ln2T, K_,
                                          (long long)N_ * K_, (long long)K_ * N_);
    float* out = (float*)d_out;

    launch_gh(ph_bm, ph_ln2T, pg_bh, nullptr, N_, K_, N_, N_, K_,
              (long long)NN_, 0, (long long)K_ * N_, 0, (long long)N_ * K_, 0,
              1, B_, 1, 0);
    launch_gh(ph_ln2, ph_W1T, nullptr, ph_hid, BN_, HID_, K_, K_, HID_,
              0,0,0,0,0,0, 1, 1, 0, 1, bh1);
    launch_gh(ph_hid, ph_W2T, pg_h, ph_hh, BN_, K_, HID_, HID_, K_,
              0,0,0,0,0,0, 1, 1, 0, 2, bh2, pg_ln2, mu_prior, pg_bh, lr);

    tr2h_kernel<<<dim3(16, 32, B_), tb>>>(pg_h, ph_hT, K_,
                                          (long long)N_ * K_, (long long)K_ * N_);
    launch_gh(ph_bm, ph_hT, pg_bh, nullptr, N_, K_, N_, N_, K_,
              (long long)NN_, 0, (long long)K_ * N_, 0, (long long)N_ * K_, 0,
              1, B_, 1, 0);
    launch_gh(ph_hh, ph_W1T, nullptr, ph_hid, BN_, HID_, K_, K_, HID_,
              0,0,0,0,0,0, 1, 1, 0, 1, bh1);
    launch_gh(ph_hid, ph_W2T, out, nullptr, BN_, K_, HID_, HID_, K_,
              0,0,0,0,0,0, 1, 1, 0, 3, bh2, pg_h, mu_prior, pg_bh, lr, pg_res, pg_ln2);

    cudaMemcpyAsync(out + BNK_, sigma_q, (size_t)BNK_ * sizeof(float),
                    cudaMemcpyDeviceToDevice);
    cudaMemcpyAsync(out + 2 * (size_t)BNK_, phi, (size_t)B_ * N_ * 3 * sizeof(float),
                    cudaMemcpyDeviceToDevice);
}

// round 11
// speedup vs baseline: 1.9063x; 1.0392x over previous
#include <cuda_runtime.h>
#include <cuda_fp16.h>
#include <math.h>
#include <stdint.h>

#define B_   4
#define N_   1024
#define K_   512
#define H_   8
#define DH_  64
#define HID_ 2048
#define KG_  (3*K_)
#define BN_  (B_*N_)
#define BNK_ (B_*N_*K_)
#define BHN_ (B_*H_*N_)
#define NN_  (N_*N_)
#define QKVW_ (3*K_)

// ---------------- device scratch ----------------
__device__ __half h_gcatT[KG_*K_];
__device__ __half h_wqkvT[QKVW_*K_];
__device__ __half h_w2qkT[2*K_*K_];
__device__ __half h_WoT[K_*K_];
__device__ __half h_W1T[HID_*K_];
__device__ __half h_W2T[K_*HID_];
__device__ __half h_sig[BNK_];
__device__ __half h_ln1[BNK_];
__device__ __half h_a1[BNK_];
__device__ __half h_mug[BNK_];
__device__ __half h_attn[BNK_];
__device__ __half h_ln2[BNK_];
__device__ __half h_hh[BNK_];
__device__ __half h_hid[BN_*HID_];
__device__ __half h_beta[33554432];
__device__ __half h_bm[B_*NN_];
__device__ __half h_Z[BN_*KG_];
__device__ __half h_Qe[BHN_*2*DH_];
__device__ __half h_Ke[BHN_*2*DH_];
__device__ __half h_o[BNK_];
__device__ __half h_qkv16[BN_*QKVW_];
__device__ float g_ln1[BNK_];
__device__ float g_qkv[BN_*QKVW_];
__device__ float g_s2[BN_*2*K_];
__device__ float g_gam[BHN_];
__device__ float g_del[BHN_];
__device__ float g_beta[33554432];
__device__ float g_o[BNK_];
__device__ float g_res[BNK_];
__device__ float g_ln2[BNK_];
__device__ float g_h[BNK_];
__device__ float g_bh[BNK_];

// ---------------- helpers ----------------
__device__ __forceinline__ float warpSum(float v) {
#pragma unroll
    for (int o = 16; o; o >>= 1) v += __shfl_down_sync(0xffffffffu, v, o);
    return v;
}
__device__ __forceinline__ float allMax(float v) {
#pragma unroll
    for (int o = 16; o; o >>= 1) v = fmaxf(v, __shfl_xor_sync(0xffffffffu, v, o));
    return v;
}
__device__ __forceinline__ float allSum(float v) {
#pragma unroll
    for (int o = 16; o; o >>= 1) v += __shfl_xor_sync(0xffffffffu, v, o);
    return v;
}
__device__ __forceinline__ void cpa16(void* s, const void* g) {
    unsigned sa = (unsigned)__cvta_generic_to_shared(s);
    asm volatile("cp.async.cg.shared.global [%0], [%1], 16;" :: "r"(sa), "l"(g));
}
__device__ __forceinline__ float gelu_f(float x) {
    float x3 = x * x * x;
    return 0.5f * x * (1.f + tanhf(0.7978845608028654f * (x + 0.044715f * x3)));
}
#define LDSM4(R, addr) \
    asm volatile("ldmatrix.sync.aligned.m8n8.x4.shared.b16 {%0,%1,%2,%3}, [%4];" \
                 : "=r"((R)[0]), "=r"((R)[1]), "=r"((R)[2]), "=r"((R)[3]) : "r"(addr))
#define LDSM4T(R, addr) \
    asm volatile("ldmatrix.sync.aligned.m8n8.x4.trans.shared.b16 {%0,%1,%2,%3}, [%4];" \
                 : "=r"((R)[0]), "=r"((R)[1]), "=r"((R)[2]), "=r"((R)[3]) : "r"(addr))
#define MMA16816(D, A, B0, B1) \
    asm volatile("mma.sync.aligned.m16n8k16.row.col.f32.f16.f16.f32 " \
                 "{%0,%1,%2,%3}, {%4,%5,%6,%7}, {%8,%9}, {%0,%1,%2,%3};" \
                 : "+f"((D)[0]), "+f"((D)[1]), "+f"((D)[2]), "+f"((D)[3]) \
                 : "r"((A)[0]), "r"((A)[1]), "r"((A)[2]), "r"((A)[3]), "r"(B0), "r"(B1))

// ============ fp16 tensor-core GEMM ============
// BT=0: B = Bt [Ncols][Kd] (K-major, ldb = row stride).  BT=1: B row-major [Kd][Ncols], ldb.
// epi: 0 fp32; 1 gelu->fp16; 2 VFE->fp32+fp16; 3 VFE+final->fp32; 4 fp16; 5 fp32+fp16
template<int BN, int BT>
__global__ __launch_bounds__(256, 2)
void gemm_h(const __half* __restrict__ A, const __half* __restrict__ Bt,
            float* __restrict__ C, __half* __restrict__ C16,
            int Kd, int lda, int ldb, int ldc,
            long long sAo, long long sAi, long long sBo, long long sBi,
            long long sCo, long long sCi, int innerDiv, int causal, int epi,
            const float* __restrict__ bias,
            const float* __restrict__ e_hin,  const float* __restrict__ e_prior,
            const float* __restrict__ e_aux,  const float* __restrict__ e_lr,
            const float* __restrict__ e_res,  const float* __restrict__ e_ln2)
{
    constexpr int BM = 128, LD = 40;
    constexpr int LDB2 = BN + 8;
    constexpr int WN = BN / 2;
    constexpr int NF = BN / 16;
    extern __shared__ __half hsm[];
    __half* sA = hsm;
    __half* sB = hsm + 3 * BM * LD;     // per-stage stride BN*LD (trans uses 32*LDB2 <= BN*LD)

    int z = blockIdx.z;
    int zo = z / innerDiv, zi = z - zo * innerDiv;
    A  += zo * sAo + zi * sAi;
    Bt += zo * sBo + zi * sBi;
    long long coff = zo * sCo + zi * sCi;

    int tid = threadIdx.x;
    int wid = tid >> 5, lane = tid & 31;
    int wm = wid & 3, wn = wid >> 2;
    int row0 = blockIdx.y * BM, col0 = blockIdx.x * BN;
    int gid = lane >> 2, tig = lane & 3;
    int l8 = lane & 7, lm = lane >> 3;
    int aRow = (lm & 1) * 8 + l8, aCol = (lm >> 1) * 8;
    int bRow, bCol;
    if (BT) { bRow = (lm & 1) * 8 + l8; bCol = (lm >> 1) * 8; }     // k-row, n-col
    else    { bRow = (lm >> 1) * 8 + l8; bCol = (lm & 1) * 8; }     // n-row, k-col

    float acc[2][NF][4];
#pragma unroll
    for (int mi = 0; mi < 2; mi++)
#pragma unroll
        for (int ni = 0; ni < NF; ni++)
#pragma unroll
            for (int r = 0; r < 4; r++) acc[mi][ni][r] = 0.f;

    int kTiles = Kd / 32;
    if (causal) { int lim = (row0 + BM) / 32; if (lim < kTiles) kTiles = lim; }

    auto loadTile = [&](int t) {
        int buf = t % 3;
        int k0 = t * 32;
        __half* pA = sA + buf * BM * LD;
        __half* pB = sB + buf * BN * LD;
#pragma unroll
        for (int i = tid; i < BM * 4; i += 256) {
            int m = i >> 2, u = i & 3;
            cpa16(&pA[m * LD + u * 8], A + (size_t)(row0 + m) * lda + k0 + u * 8);
        }
        if (BT) {
#pragma unroll
            for (int i = tid; i < BN * 4; i += 256) {
                int kk = i / (BN / 8), u = i % (BN / 8);
                cpa16(&pB[kk * LDB2 + u * 8], Bt + (size_t)(k0 + kk) * ldb + col0 + u * 8);
            }
        } else {
#pragma unroll
            for (int i = tid; i < BN * 4; i += 256) {
                int n = i >> 2, u = i & 3;
                cpa16(&pB[n * LD + u * 8], Bt + (size_t)(col0 + n) * ldb + u * 8 + k0);
            }
        }
        asm volatile("cp.async.commit_group;");
    };

    loadTile(0);
    if (kTiles > 1) loadTile(1);
    else asm volatile("cp.async.commit_group;");

    for (int t = 0; t < kTiles; t++) {
        asm volatile("cp.async.wait_group 1;");
        __syncthreads();
        if (t + 2 < kTiles) loadTile(t + 2);
        else asm volatile("cp.async.commit_group;");
        int buf = t % 3;
        const __half* pA = sA + buf * BM * LD;
        const __half* pB = sB + buf * BN * LD;
#pragma unroll
        for (int ks = 0; ks < 2; ks++) {
            int kb0 = ks * 16;
            uint32_t a[2][4];
#pragma unroll
            for (int mi = 0; mi < 2; mi++) {
                unsigned ad = (unsigned)__cvta_generic_to_shared(
                    &pA[(wm * 32 + mi * 16 + aRow) * LD + kb0 + aCol]);
                LDSM4(a[mi], ad);
            }
#pragma unroll
            for (int ni2 = 0; ni2 < NF / 2; ni2++) {
                uint32_t bb[4];
                if (BT) {
                    unsigned bd = (unsigned)__cvta_generic_to_shared(
                        &pB[(kb0 + bRow) * LDB2 + wn * WN + ni2 * 16 + bCol]);
                    LDSM4T(bb, bd);
                } else {
                    unsigned bd = (unsigned)__cvta_generic_to_shared(
                        &pB[(wn * WN + ni2 * 16 + bRow) * LD + kb0 + bCol]);
                    LDSM4(bb, bd);
                }
#pragma unroll
                for (int mi = 0; mi < 2; mi++) {
                    MMA16816(acc[mi][2 * ni2],     a[mi], bb[0], bb[1]);
                    MMA16816(acc[mi][2 * ni2 + 1], a[mi], bb[2], bb[3]);
                }
            }
        }
        __syncthreads();
    }

    float lrv = (epi == 2 || epi == 3) ? e_lr[0] : 0.f;
    bool w32 = (epi == 0 || epi == 2 || epi == 3 || epi == 5);
    bool w16 = (epi == 1 || epi == 2 || epi == 4 || epi == 5);
#pragma unroll
    for (int mi = 0; mi < 2; mi++) {
#pragma unroll
        for (int ni = 0; ni < NF; ni++) {
            int cb = col0 + wn * WN + ni * 8 + 2 * tig;
#pragma unroll
            for (int hf = 0; hf < 2; hf++) {
                int rr = row0 + wm * 32 + mi * 16 + gid + hf * 8;
                float v0 = acc[mi][ni][hf * 2], v1 = acc[mi][ni][hf * 2 + 1];
                long long off = coff + (long long)rr * ldc + cb;
                if (epi == 1) {
                    v0 = gelu_f(v0 + bias[cb]);
                    v1 = gelu_f(v1 + bias[cb + 1]);
                } else if (epi == 2 || epi == 3) {
                    float x0 = v0 + bias[cb], x1 = v1 + bias[cb + 1];
                    float h0 = e_hin[off], h1 = e_hin[off + 1];
                    v0 = h0 + lrv * (x0 - (1e-3f * (h0 - e_prior[off]) + (h0 - e_aux[off])));
                    v1 = h1 + lrv * (x1 - (1e-3f * (h1 - e_prior[off + 1]) + (h1 - e_aux[off + 1])));
                    if (epi == 3) {
                        v0 = e_res[off] + v0 - e_ln2[off];
                        v1 = e_res[off + 1] + v1 - e_ln2[off + 1];
                    }
                }
                if (w32) { float2 f2; f2.x = v0; f2.y = v1; *(float2*)&C[off] = f2; }
                if (w16) { *(__half2*)&C16[off] = __floats2half2_rn(v0, v1); }
            }
        }
    }
}

// ---------------- merged prep: two fp16 copies ----------------
__global__ void prep_copy_kernel(const float* __restrict__ gen, const float* __restrict__ sig)
{
    int i = blockIdx.x * 256 + threadIdx.x;
    if (i < KG_ * K_) h_gcatT[i] = __float2half_rn(gen[i]);
    else {
        int j = i - KG_ * K_;
        if (j < BNK_) h_sig[j] = __float2half_rn(sig[j]);
    }
}

// ---------------- merged prep: all 8 weight transposes ----------------
__global__ void prep_tr_kernel(const float* __restrict__ Wq, const float* __restrict__ Wk,
                               const float* __restrict__ Wv, const float* __restrict__ Wo,
                               const float* __restrict__ W1, const float* __restrict__ W2)
{
    // blocks: 6*256 (512x512) + 1024 (W1) + 1024 (W2) = 3584
    int lb = blockIdx.x;
    const float* src; __half* dst; int R, C, gx, sq = 0;
    if (lb < 1536) {
        int sel = lb >> 8; lb &= 255;
        R = K_; C = K_; gx = 16;
        switch (sel) {
            case 0: src = Wq; dst = h_wqkvT; break;
            case 1: src = Wk; dst = h_wqkvT + K_ * K_; break;
            case 2: src = Wv; dst = h_wqkvT + 2 * K_ * K_; break;
            case 3: src = Wq; dst = h_w2qkT; sq = 1; break;
            case 4: src = Wk; dst = h_w2qkT + K_ * K_; sq = 1; break;
            default: src = Wo; dst = h_WoT; break;
        }
    } else if (lb < 2560) {
        lb -= 1536; src = W1; dst = h_W1T; R = K_; C = HID_; gx = 64;
    } else {
        lb -= 2560; src = W2; dst = h_W2T; R = HID_; C = K_; gx = 16;
    }
    int bx = (lb % gx) * 32, by = (lb / gx) * 32;
    __shared__ float t[32][33];
    int x = bx + threadIdx.x;
#pragma unroll
    for (int i = 0; i < 32; i += 8) {
        int y = by + threadIdx.y + i;
        float v = src[(size_t)y * C + x];
        if (sq) v = v * v;
        t[threadIdx.y + i][threadIdx.x] = v;
    }
    __syncthreads();
    int xo = by + threadIdx.x;
#pragma unroll
    for (int i = 0; i < 32; i += 8) {
        int yo = bx + threadIdx.y + i;
        dst[(size_t)yo * R + xo] = __float2half_rn(t[threadIdx.x][threadIdx.y + i]);
    }
}

// ---------------- layernorm (fp32 out + fp16 twin) ----------------
__global__ void ln_kernel(const float* __restrict__ x, const float* __restrict__ gw,
                          const float* __restrict__ bw, float* __restrict__ y,
                          __half* __restrict__ yh)
{
    int bn = blockIdx.x;
    const float* xr = x + (long long)bn * K_;
    int t = threadIdx.x;
    float v0 = xr[t], v1 = xr[t + 256];
    __shared__ float red[8];
    __shared__ float s_mean, s_rstd;
    int lane = t & 31, w = t >> 5;
    float s = warpSum(v0 + v1);
    if (lane == 0) red[w] = s;
    __syncthreads();
    if (t == 0) {
        float tot = 0.f;
        for (int i = 0; i < 8; i++) tot += red[i];
        s_mean = tot * (1.f / 512.f);
    }
    __syncthreads();
    float m = s_mean;
    float d0 = v0 - m, d1 = v1 - m;
    float s2 = warpSum(d0 * d0 + d1 * d1);
    if (lane == 0) red[w] = s2;
    __syncthreads();
    if (t == 0) {
        float tot = 0.f;
        for (int i = 0; i < 8; i++) tot += red[i];
        s_rstd = rsqrtf(tot * (1.f / 512.f) + 1e-5f);
    }
    __syncthreads();
    float r = s_rstd;
    float o0 = d0 * r * gw[t] + bw[t];
    float o1 = d1 * r * gw[t + 256] + bw[t + 256];
    long long base = (long long)bn * K_;
    if (y) { y[base + t] = o0; y[base + t + 256] = o1; }
    if (yh) {
        yh[base + t] = __float2half_rn(o0);
        yh[base + t + 256] = __float2half_rn(o1);
    }
}

// ---------------- transport combines (fp16 Z) ----------------
__global__ void combine1_kernel(const float* __restrict__ phi, float sign)
{
    int i = blockIdx.x * 256 + threadIdx.x;
    if (i >= BNK_) return;
    int bn = i >> 9, k = i & (K_ - 1);
    const float* pp = phi + bn * 3;
    const __half* z = h_Z + (long long)bn * KG_;
    float v = sign * (pp[0] * __half2float(z[k]) + pp[1] * __half2float(z[K_ + k])
                    + pp[2] * __half2float(z[2 * K_ + k]));
    h_a1[i] = __float2half_rn(v);
}
__global__ void combine2_kernel(const float* __restrict__ phi, float sign,
                                const float* __restrict__ xbase,
                                const float* __restrict__ resid,
                                float* __restrict__ out32, __half* __restrict__ out16)
{
    int i = blockIdx.x * 256 + threadIdx.x;
    if (i >= BNK_) return;
    int bn = i >> 9, k = i & (K_ - 1);
    const float* pp = phi + bn * 3;
    const __half* z = h_Z + (long long)bn * KG_;
    float c = sign * (pp[0] * __half2float(z[k]) + pp[1] * __half2float(z[K_ + k])
                    + pp[2] * __half2float(z[2 * K_ + k]));
    float r = xbase[i] + __half2float(h_a1[i]) + 0.5f * c;
    if (resid) r += resid[i];
    if (out32) out32[i] = r;
    if (out16) out16[i] = __float2half_rn(r);
}

// ---------------- fused attention prep -> fp16 Qe/Ke + gamma/delta ----------------
__global__ void prep_attn_gamdel_kernel()
{
    int bn = blockIdx.x;
    int b = bn >> 10, n = bn & (N_ - 1);
    int t = threadIdx.x;
    int lane = t & 31;
    __shared__ float sacc[3][H_];
    if (t < 3 * H_) ((float*)sacc)[t] = 0.f;
    __syncthreads();
#pragma unroll
    for (int half = 0; half < 2; half++) {
        int k = t + half * 256;
        long long s2b = (long long)bn * (2 * K_);
        long long qb  = (long long)bn * QKVW_;
        float sqraw = g_s2[s2b + k] + 1e-8f;
        float inv = 1.f / sqraw;
        float q = g_qkv[qb + k];
        float sk = g_s2[s2b + K_ + k] + 1e-8f;
        float kv = g_qkv[qb + K_ + k];
        int h = k >> 6, d = k & 63;
        size_t qe = (((size_t)(b * H_ + h)) * N_ + n) * 128 + d;
        h_Qe[qe]      = __float2half_rn(-0.5f * inv);
        h_Qe[qe + 64] = __float2half_rn(q * inv);
        h_Ke[qe]      = __float2half_rn(sk + kv * kv);
        h_Ke[qe + 64] = __float2half_rn(kv);
        float qq  = q * q * inv;
        float lsq = logf(sqraw);
        float lsk = logf(sk);
        qq = warpSum(qq); lsq = warpSum(lsq); lsk = warpSum(lsk);
        if (lane == 0) {
            atomicAdd(&sacc[0][h], qq);
            atomicAdd(&sacc[1][h], lsq);
            atomicAdd(&sacc[2][h], lsk);
        }
    }
    __syncthreads();
    if (t < H_) {
        int idx = ((b * H_ + t) * N_) + n;
        g_gam[idx] = -0.5f * (sacc[0][t] - (float)DH_ + sacc[1][t]);
        g_del[idx] = 0.5f * sacc[2][t];
    }
}

// ---------------- KL score: fp16 mma + ldmatrix, 64x64 tiles, K=128 ----------------
__global__ __launch_bounds__(256) void score_kernel()
{
    int bh = blockIdx.z;
    int i0 = blockIdx.y * 64, j0 = blockIdx.x * 64;
    if (j0 > i0) return;
    constexpr int LD = 136;
    __shared__ __half Qs[64 * LD];
    __shared__ __half Ks[64 * LD];
    int tid = threadIdx.x;
    int wid = tid >> 5, lane = tid & 31;
    int wm = wid & 3, wn = wid >> 2;
    int gid = lane >> 2, tig = lane & 3;
    int l8 = lane & 7, lm = lane >> 3;
    int aRow = (lm & 1) * 8 + l8, aCol = (lm >> 1) * 8;
    int bRow = (lm >> 1) * 8 + l8, bCol = (lm & 1) * 8;

    const __half* Qsrc = h_Qe + (((size_t)bh) * N_ + i0) * 128;
    const __half* Ksrc = h_Ke + (((size_t)bh) * N_ + j0) * 128;
    for (int i = tid; i < 1024; i += 256) {
        int r = i >> 4, u = (i & 15) * 8;
        cpa16(&Qs[r * LD + u], Qsrc + (size_t)r * 128 + u);
        cpa16(&Ks[r * LD + u], Ksrc + (size_t)r * 128 + u);
    }
    asm volatile("cp.async.commit_group;");
    asm volatile("cp.async.wait_group 0;");
    __syncthreads();

    float acc[4][4] = {};
#pragma unroll
    for (int ks = 0; ks < 8; ks++) {
        int kb0 = ks * 16;
        uint32_t a[4];
        unsigned ad = (unsigned)__cvta_generic_to_shared(
            &Qs[(wm * 16 + aRow) * LD + kb0 + aCol]);
        LDSM4(a, ad);
#pragma unroll
        for (int ni2 = 0; ni2 < 2; ni2++) {
            uint32_t bb[4];
            unsigned bd = (unsigned)__cvta_generic_to_shared(
                &Ks[(wn * 32 + ni2 * 16 + bRow) * LD + kb0 + bCol]);
            LDSM4(bb, bd);
            MMA16816(acc[2 * ni2],     a, bb[0], bb[1]);
            MMA16816(acc[2 * ni2 + 1], a, bb[2], bb[3]);
        }
    }

    long long gdb = (long long)bh * N_;
#pragma unroll
    for (int hf = 0; hf < 2; hf++) {
        int i = i0 + wm * 16 + gid + hf * 8;
        float gv = g_gam[gdb + i];
#pragma unroll
        for (int ni = 0; ni < 4; ni++) {
            int j = j0 + wn * 32 + ni * 8 + 2 * tig;
            float2 o;
            o.x = acc[ni][hf * 2 + 0] + gv + g_del[gdb + j];
            o.y = acc[ni][hf * 2 + 1] + gv + g_del[gdb + j + 1];
            *(float2*)&g_beta[(gdb + i) * N_ + j] = o;
        }
    }
}

// ---------------- softmax: 1 warp per (head,row) + fused beta_m ----------------
__global__ __launch_bounds__(256) void softmax_bm_kernel()
{
    int bi = blockIdx.x;
    int b = bi >> 10, i = bi & (N_ - 1);
    int Jmax = ((i >> 7) + 1) << 7;
    int tid = threadIdx.x;
    int w = tid >> 5, lane = tid & 31;
    __shared__ float bmbuf[H_][N_];

    long long rowoff = (((long long)(b * H_ + w)) * N_ + i) * N_;
    const float* p = g_beta + rowoff;
    __half* ph = h_beta + rowoff;

    float ev[32];
    float m = -1e30f;
#pragma unroll
    for (int jj = 0; jj < 32; jj++) {
        int j = lane + jj * 32;
        float v = (j <= i) ? p[j] : -1e30f;
        ev[jj] = v;
        m = fmaxf(m, v);
    }
    m = allMax(m);
    float s = 0.f;
#pragma unroll
    for (int jj = 0; jj < 32; jj++) {
        ev[jj] = (lane + jj * 32 <= i) ? expf(ev[jj] - m) : 0.f;
        s += ev[jj];
    }
    s = allSum(s);
    float inv = 1.f / s;
#pragma unroll
    for (int jj = 0; jj < 32; jj++) {
        int j = lane + jj * 32;
        if (j < Jmax) {
            float v = ev[jj] * inv;
            ph[j] = __float2half_rn(v);
            bmbuf[w][j] = v;
        }
    }
    __syncthreads();
    __half* bm = h_bm + ((long long)b * N_ + i) * N_;
    for (int j = tid; j < Jmax; j += 256) {
        float t = 0.f;
#pragma unroll
        for (int h = 0; h < H_; h++) t += bmbuf[h][j];
        bm[j] = __float2half_rn(t * 0.125f);
    }
}

// ---------------- host ----------------
#define SM128 (3 * (128 * 40 + 128 * 40) * 2)   // 61440
#define SM64  (3 * (128 * 40 + 64 * 40) * 2)    // 46080
static inline void launch_gh(const __half* A, const __half* Bt, float* C, __half* C16,
                             int M, int Ncols, int Kd, int lda, int ldb, int ldc,
                             long long sAo, long long sAi, long long sBo, long long sBi,
                             long long sCo, long long sCi, int innerDiv, int batch,
                             int causal, int epi, int btrans,
                             const float* bias = nullptr,
                             const float* e_hin = nullptr, const float* e_prior = nullptr,
                             const float* e_aux = nullptr, const float* e_lr = nullptr,
                             const float* e_res = nullptr, const float* e_ln2 = nullptr)
{
    if (Ncols % 128 == 0) {
        dim3 g(Ncols / 128, M / 128, batch);
        if (btrans)
            gemm_h<128, 1><<<g, 256, SM128>>>(A, Bt, C, C16, Kd, lda, ldb, ldc,
                                              sAo, sAi, sBo, sBi, sCo, sCi, innerDiv, causal,
                                              epi, bias, e_hin, e_prior, e_aux, e_lr, e_res, e_ln2);
        else
            gemm_h<128, 0><<<g, 256, SM128>>>(A, Bt, C, C16, Kd, lda, ldb, ldc,
                                              sAo, sAi, sBo, sBi, sCo, sCi, innerDiv, causal,
                                              epi, bias, e_hin, e_prior, e_aux, e_lr, e_res, e_ln2);
    } else {
        dim3 g(Ncols / 64, M / 128, batch);
        if (btrans)
            gemm_h<64, 1><<<g, 256, SM64>>>(A, Bt, C, C16, Kd, lda, ldb, ldc,
                                            sAo, sAi, sBo, sBi, sCo, sCi, innerDiv, causal,
                                            epi, bias, e_hin, e_prior, e_aux, e_lr, e_res, e_ln2);
        else
            gemm_h<64, 0><<<g, 256, SM64>>>(A, Bt, C, C16, Kd, lda, ldb, ldc,
                                            sAo, sAi, sBo, sBi, sCo, sCi, innerDiv, causal,
                                            epi, bias, e_hin, e_prior, e_aux, e_lr, e_res, e_ln2);
    }
}

extern "C" void kernel_launch(void* const* d_in, const int* in_sizes, int n_in,
                              void* d_out, int out_size)
{
    const float* mu_q     = (const float*)d_in[0];
    const float* sigma_q  = (const float*)d_in[1];
    const float* phi      = (const float*)d_in[2];
    const float* gen      = (const float*)d_in[3];
    const float* mu_prior = (const float*)d_in[5];
    const float* Wq  = (const float*)d_in[6];
    const float* Wk  = (const float*)d_in[7];
    const float* Wv  = (const float*)d_in[8];
    const float* Wo  = (const float*)d_in[9];
    const float* g1  = (const float*)d_in[10];
    const float* be1 = (const float*)d_in[11];
    const float* g2  = (const float*)d_in[12];
    const float* be2 = (const float*)d_in[13];
    const float* W1  = (const float*)d_in[14];
    const float* bh1 = (const float*)d_in[15];
    const float* W2  = (const float*)d_in[16];
    const float* bh2 = (const float*)d_in[17];
    const float* lr  = (const float*)d_in[18];

    static int attrDone = 0;
    if (!attrDone) {
        cudaFuncSetAttribute(gemm_h<128, 0>, cudaFuncAttributeMaxDynamicSharedMemorySize, SM128);
        cudaFuncSetAttribute(gemm_h<128, 1>, cudaFuncAttributeMaxDynamicSharedMemorySize, SM128);
        cudaFuncSetAttribute(gemm_h<64, 0>,  cudaFuncAttributeMaxDynamicSharedMemorySize, SM64);
        cudaFuncSetAttribute(gemm_h<64, 1>,  cudaFuncAttributeMaxDynamicSharedMemorySize, SM64);
        attrDone = 1;
    }

    void* tp;
#define GETSYMF(var, sym) cudaGetSymbolAddress(&tp, sym); float* var = (float*)tp
#define GETSYMH(var, sym) cudaGetSymbolAddress(&tp, sym); __half* var = (__half*)tp
    GETSYMH(ph_gcatT, h_gcatT); GETSYMH(ph_wqkvT, h_wqkvT); GETSYMH(ph_w2qkT, h_w2qkT);
    GETSYMH(ph_WoT, h_WoT);     GETSYMH(ph_W1T, h_W1T);     GETSYMH(ph_W2T, h_W2T);
    GETSYMH(ph_sig, h_sig);     GETSYMH(ph_ln1, h_ln1);     GETSYMH(ph_a1, h_a1);
    GETSYMH(ph_mug, h_mug);     GETSYMH(ph_attn, h_attn);   GETSYMH(ph_o, h_o);
    GETSYMH(ph_ln2, h_ln2);     GETSYMH(ph_hh, h_hh);       GETSYMH(ph_hid, h_hid);
    GETSYMH(ph_beta, h_beta);   GETSYMH(ph_bm, h_bm);       GETSYMH(ph_Z, h_Z);
    GETSYMH(ph_qkv16, h_qkv16);
    GETSYMF(pg_ln1, g_ln1);     GETSYMF(pg_qkv, g_qkv);     GETSYMF(pg_s2, g_s2);
    GETSYMF(pg_o, g_o);         GETSYMF(pg_res, g_res);     GETSYMF(pg_ln2, g_ln2);
    GETSYMF(pg_h, g_h);         GETSYMF(pg_bh, g_bh);
#undef GETSYMF
#undef GETSYMH

    const int EW = 256;
    const int GB_BNK = BNK_ / EW;

    // ---- merged prep (2 launches) ----
    prep_copy_kernel<<<(KG_ * K_ + BNK_ + EW - 1) / EW, EW>>>(gen, sigma_q);
    prep_tr_kernel<<<3584, dim3(32, 8)>>>(Wq, Wk, Wv, Wo, W1, W2);

    // ---- attention sublayer ----
    ln_kernel<<<BN_, 256>>>(mu_q, g1, be1, pg_ln1, ph_ln1);
    launch_gh(ph_ln1, ph_gcatT, nullptr, ph_Z, BN_, KG_, K_, K_, K_, KG_,
              0,0,0,0,0,0, 1, 1, 0, 4, 0);
    combine1_kernel<<<GB_BNK, EW>>>(phi, 1.f);
    launch_gh(ph_a1, ph_gcatT, nullptr, ph_Z, BN_, KG_, K_, K_, K_, KG_,
              0,0,0,0,0,0, 1, 1, 0, 4, 0);
    combine2_kernel<<<GB_BNK, EW>>>(phi, 1.f, pg_ln1, nullptr, nullptr, ph_mug);

    // QKV: fp32 + fp16 twin (v rows consumed directly by beta@v)
    launch_gh(ph_mug, ph_wqkvT, pg_qkv, ph_qkv16, BN_, QKVW_, K_, K_, K_, QKVW_,
              0,0,0,0,0,0, 1, 1, 0, 5, 0);
    launch_gh(ph_sig, ph_w2qkT, pg_s2, nullptr, BN_, 2 * K_, K_, K_, K_, 2 * K_,
              0,0,0,0,0,0, 1, 1, 0, 0, 0);

    prep_attn_gamdel_kernel<<<BN_, 256>>>();
    score_kernel<<<dim3(N_ / 64, N_ / 64, B_ * H_), 256>>>();
    softmax_bm_kernel<<<BN_, 256>>>();

    // attn = beta @ v  (B = v rows of h_qkv16, row-major via trans path)
    launch_gh(ph_beta, ph_qkv16 + 2 * K_, nullptr, ph_attn, N_, DH_, N_, N_, QKVW_, K_,
              8LL * NN_, (long long)NN_,
              (long long)N_ * QKVW_, 64,
              (long long)N_ * K_, 64, H_, B_ * H_, 1, 4, 1);

    launch_gh(ph_attn, ph_WoT, pg_o, ph_o, BN_, K_, K_, K_, K_, K_,
              0,0,0,0,0,0, 1, 1, 0, 5, 0);
    launch_gh(ph_o, ph_gcatT, nullptr, ph_Z, BN_, KG_, K_, K_, K_, KG_,
              0,0,0,0,0,0, 1, 1, 0, 4, 0);
    combine1_kernel<<<GB_BNK, EW>>>(phi, -1.f);
    launch_gh(ph_a1, ph_gcatT, nullptr, ph_Z, BN_, KG_, K_, K_, K_, KG_,
              0,0,0,0,0,0, 1, 1, 0, 4, 0);
    combine2_kernel<<<GB_BNK, EW>>>(phi, -1.f, pg_o, mu_q, pg_res, nullptr);

    // ---- FFN sublayer ----
    ln_kernel<<<BN_, 256>>>(pg_res, g2, be2, pg_ln2, ph_ln2);
    float* out = (float*)d_out;

    // iteration 1: bm @ ln2 (row-major B via trans), W1+gelu, W2+VFE
    launch_gh(ph_bm, ph_ln2, pg_bh, nullptr, N_, K_, N_, N_, K_, K_,
              (long long)NN_, 0, (long long)N_ * K_, 0, (long long)N_ * K_, 0,
              1, B_, 1, 0, 1);
    launch_gh(ph_ln2, ph_W1T, nullptr, ph_hid, BN_, HID_, K_, K_, K_, HID_,
              0,0,0,0,0,0, 1, 1, 0, 1, 0, bh1);
    launch_gh(ph_hid, ph_W2T, pg_h, ph_hh, BN_, K_, HID_, HID_, HID_, K_,
              0,0,0,0,0,0, 1, 1, 0, 2, 0, bh2, pg_ln2, mu_prior, pg_bh, lr);

    // iteration 2 (final residual fused -> out)
    launch_gh(ph_bm, ph_hh, pg_bh, nullptr, N_, K_, N_, N_, K_, K_,
              (long long)NN_, 0, (long long)N_ * K_, 0, (long long)N_ * K_, 0,
              1, B_, 1, 0, 1);
    launch_gh(ph_hh, ph_W1T, nullptr, ph_hid, BN_, HID_, K_, K_, K_, HID_,
              0,0,0,0,0,0, 1, 1, 0, 1, 0, bh1);
    launch_gh(ph_hid, ph_W2T, out, nullptr, BN_, K_, HID_, HID_, HID_, K_,
              0,0,0,0,0,0, 1, 1, 0, 3, 0, bh2, pg_h, mu_prior, pg_bh, lr, pg_res, pg_ln2);

    cudaMemcpyAsync(out + BNK_, sigma_q, (size_t)BNK_ * sizeof(float),
                    cudaMemcpyDeviceToDevice);
    cudaMemcpyAsync(out + 2 * (size_t)BNK_, phi, (size_t)B_ * N_ * 3 * sizeof(float),
                    cudaMemcpyDeviceToDevice);
}

// round 12
// speedup vs baseline: 2.0133x; 1.0561x over previous
#include <cuda_runtime.h>
#include <cuda_fp16.h>
#include <math.h>
#include <stdint.h>

#define B_   4
#define N_   1024
#define K_   512
#define H_   8
#define DH_  64
#define HID_ 2048
#define KG_  (3*K_)
#define BN_  (B_*N_)
#define BNK_ (B_*N_*K_)
#define BHN_ (B_*H_*N_)
#define NN_  (N_*N_)
#define QKVW_ (3*K_)

// ---------------- device scratch ----------------
__device__ __half h_gcatT[KG_*K_];
__device__ __half h_wqkvT[QKVW_*K_];
__device__ __half h_w2qkT[2*K_*K_];
__device__ __half h_WoT[K_*K_];
__device__ __half h_W1T[HID_*K_];
__device__ __half h_W2T[K_*HID_];
__device__ __half h_sig[BNK_];
__device__ __half h_ln1[BNK_];
__device__ __half h_a1[BNK_];
__device__ __half h_mug[BNK_];
__device__ __half h_attn[BNK_];
__device__ __half h_ln2[BNK_];
__device__ __half h_hh[BNK_];
__device__ __half h_hid[BN_*HID_];
__device__ __half h_beta[33554432];
__device__ __half h_bm[B_*NN_];
__device__ __half h_Z[BN_*KG_];
__device__ __half h_Qe[BHN_*2*DH_];
__device__ __half h_Ke[BHN_*2*DH_];
__device__ __half h_o[BNK_];
__device__ __half h_qkv16[BN_*QKVW_];
__device__ float g_ln1[BNK_];
__device__ float g_qkv[BN_*QKVW_];
__device__ float g_s2[BN_*2*K_];
__device__ float g_gam[BHN_];
__device__ float g_del[BHN_];
__device__ float g_beta[33554432];
__device__ float g_o[BNK_];
__device__ float g_res[BNK_];
__device__ float g_ln2[BNK_];
__device__ float g_h[BNK_];
__device__ float g_bh[BNK_];

// ---------------- helpers ----------------
__device__ __forceinline__ float warpSum(float v) {
#pragma unroll
    for (int o = 16; o; o >>= 1) v += __shfl_down_sync(0xffffffffu, v, o);
    return v;
}
__device__ __forceinline__ float allMax(float v) {
#pragma unroll
    for (int o = 16; o; o >>= 1) v = fmaxf(v, __shfl_xor_sync(0xffffffffu, v, o));
    return v;
}
__device__ __forceinline__ float allSum(float v) {
#pragma unroll
    for (int o = 16; o; o >>= 1) v += __shfl_xor_sync(0xffffffffu, v, o);
    return v;
}
__device__ __forceinline__ void cpa16(void* s, const void* g) {
    unsigned sa = (unsigned)__cvta_generic_to_shared(s);
    asm volatile("cp.async.cg.shared.global [%0], [%1], 16;" :: "r"(sa), "l"(g));
}
__device__ __forceinline__ float gelu_f(float x) {
    float x3 = x * x * x;
    return 0.5f * x * (1.f + tanhf(0.7978845608028654f * (x + 0.044715f * x3)));
}
#define LDSM4(R, addr) \
    asm volatile("ldmatrix.sync.aligned.m8n8.x4.shared.b16 {%0,%1,%2,%3}, [%4];" \
                 : "=r"((R)[0]), "=r"((R)[1]), "=r"((R)[2]), "=r"((R)[3]) : "r"(addr))
#define LDSM4T(R, addr) \
    asm volatile("ldmatrix.sync.aligned.m8n8.x4.trans.shared.b16 {%0,%1,%2,%3}, [%4];" \
                 : "=r"((R)[0]), "=r"((R)[1]), "=r"((R)[2]), "=r"((R)[3]) : "r"(addr))
#define MMA16816(D, A, B0, B1) \
    asm volatile("mma.sync.aligned.m16n8k16.row.col.f32.f16.f16.f32 " \
                 "{%0,%1,%2,%3}, {%4,%5,%6,%7}, {%8,%9}, {%0,%1,%2,%3};" \
                 : "+f"((D)[0]), "+f"((D)[1]), "+f"((D)[2]), "+f"((D)[3]) \
                 : "r"((A)[0]), "r"((A)[1]), "r"((A)[2]), "r"((A)[3]), "r"(B0), "r"(B1))

// ============ fp16 tensor-core GEMM, BK=64, 3-stage, single barrier per K-tile ============
// BT=0: B = Bt [Ncols][Kd] (K-major, ldb = row stride).  BT=1: B row-major [Kd][Ncols], ldb.
// epi: 0 fp32; 1 gelu->fp16; 2 VFE->fp32+fp16; 3 VFE+final->fp32; 4 fp16; 5 fp32+fp16
template<int BN, int BT>
__global__ __launch_bounds__(256, 2)
void gemm_h(const __half* __restrict__ A, const __half* __restrict__ Bt,
            float* __restrict__ C, __half* __restrict__ C16,
            int Kd, int lda, int ldb, int ldc,
            long long sAo, long long sAi, long long sBo, long long sBi,
            long long sCo, long long sCi, int innerDiv, int causal, int epi,
            const float* __restrict__ bias,
            const float* __restrict__ e_hin,  const float* __restrict__ e_prior,
            const float* __restrict__ e_aux,  const float* __restrict__ e_lr,
            const float* __restrict__ e_res,  const float* __restrict__ e_ln2)
{
    constexpr int BM = 128, LD = 72;    // 64 k-halves + 8 pad
    constexpr int LDB2 = BN + 8;
    constexpr int WN = BN / 2;
    constexpr int NF = BN / 16;
    extern __shared__ __half hsm[];
    __half* sA = hsm;                   // 3 stages of BM*LD
    __half* sB = hsm + 3 * BM * LD;     // 3 stages of BN*LD (BT=1 uses 64*LDB2 <= BN*LD)

    int z = blockIdx.z;
    int zo = z / innerDiv, zi = z - zo * innerDiv;
    A  += zo * sAo + zi * sAi;
    Bt += zo * sBo + zi * sBi;
    long long coff = zo * sCo + zi * sCi;

    int tid = threadIdx.x;
    int wid = tid >> 5, lane = tid & 31;
    int wm = wid & 3, wn = wid >> 2;
    int row0 = blockIdx.y * BM, col0 = blockIdx.x * BN;
    int gid = lane >> 2, tig = lane & 3;
    int l8 = lane & 7, lm = lane >> 3;
    int aRow = (lm & 1) * 8 + l8, aCol = (lm >> 1) * 8;
    int bRow, bCol;
    if (BT) { bRow = (lm & 1) * 8 + l8; bCol = (lm >> 1) * 8; }
    else    { bRow = (lm >> 1) * 8 + l8; bCol = (lm & 1) * 8; }

    float acc[2][NF][4];
#pragma unroll
    for (int mi = 0; mi < 2; mi++)
#pragma unroll
        for (int ni = 0; ni < NF; ni++)
#pragma unroll
            for (int r = 0; r < 4; r++) acc[mi][ni][r] = 0.f;

    int kTiles = Kd / 64;
    if (causal) { int lim = (row0 + BM) / 64; if (lim < kTiles) kTiles = lim; }

    auto loadTile = [&](int t) {
        int buf = t % 3;
        int k0 = t * 64;
        __half* pA = sA + buf * BM * LD;
        __half* pB = sB + buf * BN * LD;
#pragma unroll
        for (int i = tid; i < BM * 8; i += 256) {
            int m = i >> 3, u = i & 7;
            cpa16(&pA[m * LD + u * 8], A + (size_t)(row0 + m) * lda + k0 + u * 8);
        }
        if (BT) {
            constexpr int PER = BN / 8;
#pragma unroll
            for (int i = tid; i < 64 * PER; i += 256) {
                int kk = i / PER, u = i % PER;
                cpa16(&pB[kk * LDB2 + u * 8], Bt + (size_t)(k0 + kk) * ldb + col0 + u * 8);
            }
        } else {
#pragma unroll
            for (int i = tid; i < BN * 8; i += 256) {
                int n = i >> 3, u = i & 7;
                cpa16(&pB[n * LD + u * 8], Bt + (size_t)(col0 + n) * ldb + k0 + u * 8);
            }
        }
        asm volatile("cp.async.commit_group;");
    };

    loadTile(0);
    if (kTiles > 1) loadTile(1);
    else asm volatile("cp.async.commit_group;");

    for (int t = 0; t < kTiles; t++) {
        asm volatile("cp.async.wait_group 1;");
        __syncthreads();                 // single barrier per K-tile (3-stage safe)
        if (t + 2 < kTiles) loadTile(t + 2);
        else asm volatile("cp.async.commit_group;");
        int buf = t % 3;
        const __half* pA = sA + buf * BM * LD;
        const __half* pB = sB + buf * BN * LD;
#pragma unroll
        for (int ks = 0; ks < 4; ks++) {
            int kb0 = ks * 16;
            uint32_t a[2][4];
#pragma unroll
            for (int mi = 0; mi < 2; mi++) {
                unsigned ad = (unsigned)__cvta_generic_to_shared(
                    &pA[(wm * 32 + mi * 16 + aRow) * LD + kb0 + aCol]);
                LDSM4(a[mi], ad);
            }
#pragma unroll
            for (int ni2 = 0; ni2 < NF / 2; ni2++) {
                uint32_t bb[4];
                if (BT) {
                    unsigned bd = (unsigned)__cvta_generic_to_shared(
                        &pB[(kb0 + bRow) * LDB2 + wn * WN + ni2 * 16 + bCol]);
                    LDSM4T(bb, bd);
                } else {
                    unsigned bd = (unsigned)__cvta_generic_to_shared(
                        &pB[(wn * WN + ni2 * 16 + bRow) * LD + kb0 + bCol]);
                    LDSM4(bb, bd);
                }
#pragma unroll
                for (int mi = 0; mi < 2; mi++) {
                    MMA16816(acc[mi][2 * ni2],     a[mi], bb[0], bb[1]);
                    MMA16816(acc[mi][2 * ni2 + 1], a[mi], bb[2], bb[3]);
                }
            }
        }
    }
    __syncthreads();

    float lrv = (epi == 2 || epi == 3) ? e_lr[0] : 0.f;
    bool w32 = (epi == 0 || epi == 2 || epi == 3 || epi == 5);
    bool w16 = (epi == 1 || epi == 2 || epi == 4 || epi == 5);
#pragma unroll
    for (int mi = 0; mi < 2; mi++) {
#pragma unroll
        for (int ni = 0; ni < NF; ni++) {
            int cb = col0 + wn * WN + ni * 8 + 2 * tig;
#pragma unroll
            for (int hf = 0; hf < 2; hf++) {
                int rr = row0 + wm * 32 + mi * 16 + gid + hf * 8;
                float v0 = acc[mi][ni][hf * 2], v1 = acc[mi][ni][hf * 2 + 1];
                long long off = coff + (long long)rr * ldc + cb;
                if (epi == 1) {
                    v0 = gelu_f(v0 + bias[cb]);
                    v1 = gelu_f(v1 + bias[cb + 1]);
                } else if (epi == 2 || epi == 3) {
                    float x0 = v0 + bias[cb], x1 = v1 + bias[cb + 1];
                    float h0 = e_hin[off], h1 = e_hin[off + 1];
                    v0 = h0 + lrv * (x0 - (1e-3f * (h0 - e_prior[off]) + (h0 - e_aux[off])));
                    v1 = h1 + lrv * (x1 - (1e-3f * (h1 - e_prior[off + 1]) + (h1 - e_aux[off + 1])));
                    if (epi == 3) {
                        v0 = e_res[off] + v0 - e_ln2[off];
                        v1 = e_res[off + 1] + v1 - e_ln2[off + 1];
                    }
                }
                if (w32) { float2 f2; f2.x = v0; f2.y = v1; *(float2*)&C[off] = f2; }
                if (w16) { *(__half2*)&C16[off] = __floats2half2_rn(v0, v1); }
            }
        }
    }
}

// ---------------- merged prep: two fp16 copies ----------------
__global__ void prep_copy_kernel(const float* __restrict__ gen, const float* __restrict__ sig)
{
    int i = blockIdx.x * 256 + threadIdx.x;
    if (i < KG_ * K_) h_gcatT[i] = __float2half_rn(gen[i]);
    else {
        int j = i - KG_ * K_;
        if (j < BNK_) h_sig[j] = __float2half_rn(sig[j]);
    }
}

// ---------------- merged prep: all 8 weight transposes ----------------
__global__ void prep_tr_kernel(const float* __restrict__ Wq, const float* __restrict__ Wk,
                               const float* __restrict__ Wv, const float* __restrict__ Wo,
                               const float* __restrict__ W1, const float* __restrict__ W2)
{
    int lb = blockIdx.x;
    const float* src; __half* dst; int R, C, gx, sq = 0;
    if (lb < 1536) {
        int sel = lb >> 8; lb &= 255;
        R = K_; C = K_; gx = 16;
        switch (sel) {
            case 0: src = Wq; dst = h_wqkvT; break;
            case 1: src = Wk; dst = h_wqkvT + K_ * K_; break;
            case 2: src = Wv; dst = h_wqkvT + 2 * K_ * K_; break;
            case 3: src = Wq; dst = h_w2qkT; sq = 1; break;
            case 4: src = Wk; dst = h_w2qkT + K_ * K_; sq = 1; break;
            default: src = Wo; dst = h_WoT; break;
        }
    } else if (lb < 2560) {
        lb -= 1536; src = W1; dst = h_W1T; R = K_; C = HID_; gx = 64;
    } else {
        lb -= 2560; src = W2; dst = h_W2T; R = HID_; C = K_; gx = 16;
    }
    int bx = (lb % gx) * 32, by = (lb / gx) * 32;
    __shared__ float t[32][33];
    int x = bx + threadIdx.x;
#pragma unroll
    for (int i = 0; i < 32; i += 8) {
        int y = by + threadIdx.y + i;
        float v = src[(size_t)y * C + x];
        if (sq) v = v * v;
        t[threadIdx.y + i][threadIdx.x] = v;
    }
    __syncthreads();
    int xo = by + threadIdx.x;
#pragma unroll
    for (int i = 0; i < 32; i += 8) {
        int yo = bx + threadIdx.y + i;
        dst[(size_t)yo * R + xo] = __float2half_rn(t[threadIdx.x][threadIdx.y + i]);
    }
}

// ---------------- layernorm (fp32 out + fp16 twin) ----------------
__global__ void ln_kernel(const float* __restrict__ x, const float* __restrict__ gw,
                          const float* __restrict__ bw, float* __restrict__ y,
                          __half* __restrict__ yh)
{
    int bn = blockIdx.x;
    const float* xr = x + (long long)bn * K_;
    int t = threadIdx.x;
    float v0 = xr[t], v1 = xr[t + 256];
    __shared__ float red[8];
    __shared__ float s_mean, s_rstd;
    int lane = t & 31, w = t >> 5;
    float s = warpSum(v0 + v1);
    if (lane == 0) red[w] = s;
    __syncthreads();
    if (t == 0) {
        float tot = 0.f;
        for (int i = 0; i < 8; i++) tot += red[i];
        s_mean = tot * (1.f / 512.f);
    }
    __syncthreads();
    float m = s_mean;
    float d0 = v0 - m, d1 = v1 - m;
    float s2 = warpSum(d0 * d0 + d1 * d1);
    if (lane == 0) red[w] = s2;
    __syncthreads();
    if (t == 0) {
        float tot = 0.f;
        for (int i = 0; i < 8; i++) tot += red[i];
        s_rstd = rsqrtf(tot * (1.f / 512.f) + 1e-5f);
    }
    __syncthreads();
    float r = s_rstd;
    float o0 = d0 * r * gw[t] + bw[t];
    float o1 = d1 * r * gw[t + 256] + bw[t + 256];
    long long base = (long long)bn * K_;
    if (y) { y[base + t] = o0; y[base + t + 256] = o1; }
    if (yh) {
        yh[base + t] = __float2half_rn(o0);
        yh[base + t + 256] = __float2half_rn(o1);
    }
}

// ---------------- transport combines (fp16 Z) ----------------
__global__ void combine1_kernel(const float* __restrict__ phi, float sign)
{
    int i = blockIdx.x * 256 + threadIdx.x;
    if (i >= BNK_) return;
    int bn = i >> 9, k = i & (K_ - 1);
    const float* pp = phi + bn * 3;
    const __half* z = h_Z + (long long)bn * KG_;
    float v = sign * (pp[0] * __half2float(z[k]) + pp[1] * __half2float(z[K_ + k])
                    + pp[2] * __half2float(z[2 * K_ + k]));
    h_a1[i] = __float2half_rn(v);
}
__global__ void combine2_kernel(const float* __restrict__ phi, float sign,
                                const float* __restrict__ xbase,
                                const float* __restrict__ resid,
                                float* __restrict__ out32, __half* __restrict__ out16)
{
    int i = blockIdx.x * 256 + threadIdx.x;
    if (i >= BNK_) return;
    int bn = i >> 9, k = i & (K_ - 1);
    const float* pp = phi + bn * 3;
    const __half* z = h_Z + (long long)bn * KG_;
    float c = sign * (pp[0] * __half2float(z[k]) + pp[1] * __half2float(z[K_ + k])
                    + pp[2] * __half2float(z[2 * K_ + k]));
    float r = xbase[i] + __half2float(h_a1[i]) + 0.5f * c;
    if (resid) r += resid[i];
    if (out32) out32[i] = r;
    if (out16) out16[i] = __float2half_rn(r);
}

// ---------------- fused attention prep -> fp16 Qe/Ke + gamma/delta ----------------
__global__ void prep_attn_gamdel_kernel()
{
    int bn = blockIdx.x;
    int b = bn >> 10, n = bn & (N_ - 1);
    int t = threadIdx.x;
    int lane = t & 31;
    __shared__ float sacc[3][H_];
    if (t < 3 * H_) ((float*)sacc)[t] = 0.f;
    __syncthreads();
#pragma unroll
    for (int half = 0; half < 2; half++) {
        int k = t + half * 256;
        long long s2b = (long long)bn * (2 * K_);
        long long qb  = (long long)bn * QKVW_;
        float sqraw = g_s2[s2b + k] + 1e-8f;
        float inv = 1.f / sqraw;
        float q = g_qkv[qb + k];
        float sk = g_s2[s2b + K_ + k] + 1e-8f;
        float kv = g_qkv[qb + K_ + k];
        int h = k >> 6, d = k & 63;
        size_t qe = (((size_t)(b * H_ + h)) * N_ + n) * 128 + d;
        h_Qe[qe]      = __float2half_rn(-0.5f * inv);
        h_Qe[qe + 64] = __float2half_rn(q * inv);
        h_Ke[qe]      = __float2half_rn(sk + kv * kv);
        h_Ke[qe + 64] = __float2half_rn(kv);
        float qq  = q * q * inv;
        float lsq = logf(sqraw);
        float lsk = logf(sk);
        qq = warpSum(qq); lsq = warpSum(lsq); lsk = warpSum(lsk);
        if (lane == 0) {
            atomicAdd(&sacc[0][h], qq);
            atomicAdd(&sacc[1][h], lsq);
            atomicAdd(&sacc[2][h], lsk);
        }
    }
    __syncthreads();
    if (t < H_) {
        int idx = ((b * H_ + t) * N_) + n;
        g_gam[idx] = -0.5f * (sacc[0][t] - (float)DH_ + sacc[1][t]);
        g_del[idx] = 0.5f * sacc[2][t];
    }
}

// ---------------- KL score: fp16 mma + ldmatrix, 64x64 tiles, K=128 ----------------
__global__ __launch_bounds__(256) void score_kernel()
{
    int bh = blockIdx.z;
    int i0 = blockIdx.y * 64, j0 = blockIdx.x * 64;
    if (j0 > i0) return;
    constexpr int LD = 136;
    __shared__ __half Qs[64 * LD];
    __shared__ __half Ks[64 * LD];
    int tid = threadIdx.x;
    int wid = tid >> 5, lane = tid & 31;
    int wm = wid & 3, wn = wid >> 2;
    int gid = lane >> 2, tig = lane & 3;
    int l8 = lane & 7, lm = lane >> 3;
    int aRow = (lm & 1) * 8 + l8, aCol = (lm >> 1) * 8;
    int bRow = (lm >> 1) * 8 + l8, bCol = (lm & 1) * 8;

    const __half* Qsrc = h_Qe + (((size_t)bh) * N_ + i0) * 128;
    const __half* Ksrc = h_Ke + (((size_t)bh) * N_ + j0) * 128;
    for (int i = tid; i < 1024; i += 256) {
        int r = i >> 4, u = (i & 15) * 8;
        cpa16(&Qs[r * LD + u], Qsrc + (size_t)r * 128 + u);
        cpa16(&Ks[r * LD + u], Ksrc + (size_t)r * 128 + u);
    }
    asm volatile("cp.async.commit_group;");
    asm volatile("cp.async.wait_group 0;");
    __syncthreads();

    float acc[4][4] = {};
#pragma unroll
    for (int ks = 0; ks < 8; ks++) {
        int kb0 = ks * 16;
        uint32_t a[4];
        unsigned ad = (unsigned)__cvta_generic_to_shared(
            &Qs[(wm * 16 + aRow) * LD + kb0 + aCol]);
        LDSM4(a, ad);
#pragma unroll
        for (int ni2 = 0; ni2 < 2; ni2++) {
            uint32_t bb[4];
            unsigned bd = (unsigned)__cvta_generic_to_shared(
                &Ks[(wn * 32 + ni2 * 16 + bRow) * LD + kb0 + bCol]);
            LDSM4(bb, bd);
            MMA16816(acc[2 * ni2],     a, bb[0], bb[1]);
            MMA16816(acc[2 * ni2 + 1], a, bb[2], bb[3]);
        }
    }

    long long gdb = (long long)bh * N_;
#pragma unroll
    for (int hf = 0; hf < 2; hf++) {
        int i = i0 + wm * 16 + gid + hf * 8;
        float gv = g_gam[gdb + i];
#pragma unroll
        for (int ni = 0; ni < 4; ni++) {
            int j = j0 + wn * 32 + ni * 8 + 2 * tig;
            float2 o;
            o.x = acc[ni][hf * 2 + 0] + gv + g_del[gdb + j];
            o.y = acc[ni][hf * 2 + 1] + gv + g_del[gdb + j + 1];
            *(float2*)&g_beta[(gdb + i) * N_ + j] = o;
        }
    }
}

// ---------------- softmax: 1 warp per (head,row) + fused beta_m ----------------
__global__ __launch_bounds__(256) void softmax_bm_kernel()
{
    int bi = blockIdx.x;
    int b = bi >> 10, i = bi & (N_ - 1);
    int Jmax = ((i >> 7) + 1) << 7;
    int tid = threadIdx.x;
    int w = tid >> 5, lane = tid & 31;
    __shared__ float bmbuf[H_][N_];

    long long rowoff = (((long long)(b * H_ + w)) * N_ + i) * N_;
    const float* p = g_beta + rowoff;
    __half* ph = h_beta + rowoff;

    float ev[32];
    float m = -1e30f;
#pragma unroll
    for (int jj = 0; jj < 32; jj++) {
        int j = lane + jj * 32;
        float v = (j <= i) ? p[j] : -1e30f;
        ev[jj] = v;
        m = fmaxf(m, v);
    }
    m = allMax(m);
    float s = 0.f;
#pragma unroll
    for (int jj = 0; jj < 32; jj++) {
        ev[jj] = (lane + jj * 32 <= i) ? expf(ev[jj] - m) : 0.f;
        s += ev[jj];
    }
    s = allSum(s);
    float inv = 1.f / s;
#pragma unroll
    for (int jj = 0; jj < 32; jj++) {
        int j = lane + jj * 32;
        if (j < Jmax) {
            float v = ev[jj] * inv;
            ph[j] = __float2half_rn(v);
            bmbuf[w][j] = v;
        }
    }
    __syncthreads();
    __half* bm = h_bm + ((long long)b * N_ + i) * N_;
    for (int j = tid; j < Jmax; j += 256) {
        float t = 0.f;
#pragma unroll
        for (int h = 0; h < H_; h++) t += bmbuf[h][j];
        bm[j] = __float2half_rn(t * 0.125f);
    }
}

// ---------------- host ----------------
#define SM128 (3 * (128 * 72 + 128 * 72) * 2)   // 110592
#define SM64  (3 * (128 * 72 + 64 * 72) * 2)    // 82944
static inline void launch_gh(const __half* A, const __half* Bt, float* C, __half* C16,
                             int M, int Ncols, int Kd, int lda, int ldb, int ldc,
                             long long sAo, long long sAi, long long sBo, long long sBi,
                             long long sCo, long long sCi, int innerDiv, int batch,
                             int causal, int epi, int btrans,
                             const float* bias = nullptr,
                             const float* e_hin = nullptr, const float* e_prior = nullptr,
                             const float* e_aux = nullptr, const float* e_lr = nullptr,
                             const float* e_res = nullptr, const float* e_ln2 = nullptr)
{
    if (Ncols % 128 == 0) {
        dim3 g(Ncols / 128, M / 128, batch);
        if (btrans)
            gemm_h<128, 1><<<g, 256, SM128>>>(A, Bt, C, C16, Kd, lda, ldb, ldc,
                                              sAo, sAi, sBo, sBi, sCo, sCi, innerDiv, causal,
                                              epi, bias, e_hin, e_prior, e_aux, e_lr, e_res, e_ln2);
        else
            gemm_h<128, 0><<<g, 256, SM128>>>(A, Bt, C, C16, Kd, lda, ldb, ldc,
                                              sAo, sAi, sBo, sBi, sCo, sCi, innerDiv, causal,
                                              epi, bias, e_hin, e_prior, e_aux, e_lr, e_res, e_ln2);
    } else {
        dim3 g(Ncols / 64, M / 128, batch);
        if (btrans)
            gemm_h<64, 1><<<g, 256, SM64>>>(A, Bt, C, C16, Kd, lda, ldb, ldc,
                                            sAo, sAi, sBo, sBi, sCo, sCi, innerDiv, causal,
                                            epi, bias, e_hin, e_prior, e_aux, e_lr, e_res, e_ln2);
        else
            gemm_h<64, 0><<<g, 256, SM64>>>(A, Bt, C, C16, Kd, lda, ldb, ldc,
                                            sAo, sAi, sBo, sBi, sCo, sCi, innerDiv, causal,
                                            epi, bias, e_hin, e_prior, e_aux, e_lr, e_res, e_ln2);
    }
}

extern "C" void kernel_launch(void* const* d_in, const int* in_sizes, int n_in,
                              void* d_out, int out_size)
{
    const float* mu_q     = (const float*)d_in[0];
    const float* sigma_q  = (const float*)d_in[1];
    const float* phi      = (const float*)d_in[2];
    const float* gen      = (const float*)d_in[3];
    const float* mu_prior = (const float*)d_in[5];
    const float* Wq  = (const float*)d_in[6];
    const float* Wk  = (const float*)d_in[7];
    const float* Wv  = (const float*)d_in[8];
    const float* Wo  = (const float*)d_in[9];
    const float* g1  = (const float*)d_in[10];
    const float* be1 = (const float*)d_in[11];
    const float* g2  = (const float*)d_in[12];
    const float* be2 = (const float*)d_in[13];
    const float* W1  = (const float*)d_in[14];
    const float* bh1 = (const float*)d_in[15];
    const float* W2  = (const float*)d_in[16];
    const float* bh2 = (const float*)d_in[17];
    const float* lr  = (const float*)d_in[18];

    static int attrDone = 0;
    if (!attrDone) {
        cudaFuncSetAttribute(gemm_h<128, 0>, cudaFuncAttributeMaxDynamicSharedMemorySize, SM128);
        cudaFuncSetAttribute(gemm_h<128, 1>, cudaFuncAttributeMaxDynamicSharedMemorySize, SM128);
        cudaFuncSetAttribute(gemm_h<64, 0>,  cudaFuncAttributeMaxDynamicSharedMemorySize, SM64);
        cudaFuncSetAttribute(gemm_h<64, 1>,  cudaFuncAttributeMaxDynamicSharedMemorySize, SM64);
        attrDone = 1;
    }

    void* tp;
#define GETSYMF(var, sym) cudaGetSymbolAddress(&tp, sym); float* var = (float*)tp
#define GETSYMH(var, sym) cudaGetSymbolAddress(&tp, sym); __half* var = (__half*)tp
    GETSYMH(ph_gcatT, h_gcatT); GETSYMH(ph_wqkvT, h_wqkvT); GETSYMH(ph_w2qkT, h_w2qkT);
    GETSYMH(ph_WoT, h_WoT);     GETSYMH(ph_W1T, h_W1T);     GETSYMH(ph_W2T, h_W2T);
    GETSYMH(ph_sig, h_sig);     GETSYMH(ph_ln1, h_ln1);     GETSYMH(ph_a1, h_a1);
    GETSYMH(ph_mug, h_mug);     GETSYMH(ph_attn, h_attn);   GETSYMH(ph_o, h_o);
    GETSYMH(ph_ln2, h_ln2);     GETSYMH(ph_hh, h_hh);       GETSYMH(ph_hid, h_hid);
    GETSYMH(ph_beta, h_beta);   GETSYMH(ph_bm, h_bm);       GETSYMH(ph_Z, h_Z);
    GETSYMH(ph_qkv16, h_qkv16);
    GETSYMF(pg_ln1, g_ln1);     GETSYMF(pg_qkv, g_qkv);     GETSYMF(pg_s2, g_s2);
    GETSYMF(pg_o, g_o);         GETSYMF(pg_res, g_res);     GETSYMF(pg_ln2, g_ln2);
    GETSYMF(pg_h, g_h);         GETSYMF(pg_bh, g_bh);
#undef GETSYMF
#undef GETSYMH

    const int EW = 256;
    const int GB_BNK = BNK_ / EW;

    // ---- merged prep (2 launches) ----
    prep_copy_kernel<<<(KG_ * K_ + BNK_ + EW - 1) / EW, EW>>>(gen, sigma_q);
    prep_tr_kernel<<<3584, dim3(32, 8)>>>(Wq, Wk, Wv, Wo, W1, W2);

    // ---- attention sublayer ----
    ln_kernel<<<BN_, 256>>>(mu_q, g1, be1, pg_ln1, ph_ln1);
    launch_gh(ph_ln1, ph_gcatT, nullptr, ph_Z, BN_, KG_, K_, K_, K_, KG_,
              0,0,0,0,0,0, 1, 1, 0, 4, 0);
    combine1_kernel<<<GB_BNK, EW>>>(phi, 1.f);
    launch_gh(ph_a1, ph_gcatT, nullptr, ph_Z, BN_, KG_, K_, K_, K_, KG_,
              0,0,0,0,0,0, 1, 1, 0, 4, 0);
    combine2_kernel<<<GB_BNK, EW>>>(phi, 1.f, pg_ln1, nullptr, nullptr, ph_mug);

    launch_gh(ph_mug, ph_wqkvT, pg_qkv, ph_qkv16, BN_, QKVW_, K_, K_, K_, QKVW_,
              0,0,0,0,0,0, 1, 1, 0, 5, 0);
    launch_gh(ph_sig, ph_w2qkT, pg_s2, nullptr, BN_, 2 * K_, K_, K_, K_, 2 * K_,
              0,0,0,0,0,0, 1, 1, 0, 0, 0);

    prep_attn_gamdel_kernel<<<BN_, 256>>>();
    score_kernel<<<dim3(N_ / 64, N_ / 64, B_ * H_), 256>>>();
    softmax_bm_kernel<<<BN_, 256>>>();

    launch_gh(ph_beta, ph_qkv16 + 2 * K_, nullptr, ph_attn, N_, DH_, N_, N_, QKVW_, K_,
              8LL * NN_, (long long)NN_,
              (long long)N_ * QKVW_, 64,
              (long long)N_ * K_, 64, H_, B_ * H_, 1, 4, 1);

    launch_gh(ph_attn, ph_WoT, pg_o, ph_o, BN_, K_, K_, K_, K_, K_,
              0,0,0,0,0,0, 1, 1, 0, 5, 0);
    launch_gh(ph_o, ph_gcatT, nullptr, ph_Z, BN_, KG_, K_, K_, K_, KG_,
              0,0,0,0,0,0, 1, 1, 0, 4, 0);
    combine1_kernel<<<GB_BNK, EW>>>(phi, -1.f);
    launch_gh(ph_a1, ph_gcatT, nullptr, ph_Z, BN_, KG_, K_, K_, K_, KG_,
              0,0,0,0,0,0, 1, 1, 0, 4, 0);
    combine2_kernel<<<GB_BNK, EW>>>(phi, -1.f, pg_o, mu_q, pg_res, nullptr);

    // ---- FFN sublayer ----
    ln_kernel<<<BN_, 256>>>(pg_res, g2, be2, pg_ln2, ph_ln2);
    float* out = (float*)d_out;

    launch_gh(ph_bm, ph_ln2, pg_bh, nullptr, N_, K_, N_, N_, K_, K_,
              (long long)NN_, 0, (long long)N_ * K_, 0, (long long)N_ * K_, 0,
              1, B_, 1, 0, 1);
    launch_gh(ph_ln2, ph_W1T, nullptr, ph_hid, BN_, HID_, K_, K_, K_, HID_,
              0,0,0,0,0,0, 1, 1, 0, 1, 0, bh1);
    launch_gh(ph_hid, ph_W2T, pg_h, ph_hh, BN_, K_, HID_, HID_, HID_, K_,
              0,0,0,0,0,0, 1, 1, 0, 2, 0, bh2, pg_ln2, mu_prior, pg_bh, lr);

    launch_gh(ph_bm, ph_hh, pg_bh, nullptr, N_, K_, N_, N_, K_, K_,
              (long long)NN_, 0, (long long)N_ * K_, 0, (long long)N_ * K_, 0,
              1, B_, 1, 0, 1);
    launch_gh(ph_hh, ph_W1T, nullptr, ph_hid, BN_, HID_, K_, K_, K_, HID_,
              0,0,0,0,0,0, 1, 1, 0, 1, 0, bh1);
    launch_gh(ph_hid, ph_W2T, out, nullptr, BN_, K_, HID_, HID_, HID_, K_,
              0,0,0,0,0,0, 1, 1, 0, 3, 0, bh2, pg_h, mu_prior, pg_bh, lr, pg_res, pg_ln2);

    cudaMemcpyAsync(out + BNK_, sigma_q, (size_t)BNK_ * sizeof(float),
                    cudaMemcpyDeviceToDevice);
    cudaMemcpyAsync(out + 2 * (size_t)BNK_, phi, (size_t)B_ * N_ * 3 * sizeof(float),
                    cudaMemcpyDeviceToDevice);
}